// round 1
// baseline (speedup 1.0000x reference)
#include <cuda_runtime.h>
#include <math.h>

// Problem constants
#define B   64
#define N   2048
#define D   16
#define H   64
#define DIN 2
#define C   66          // DIN + H
#define KI  132         // 2*C
#define O   64
#define BC  (B*C)       // 4224

// ---------------- scratch (static __device__, no allocation) ----------------
__device__ float g_e[3][N][D];                     // layernormed embeddings per gate
__device__ float g_bias[3][N][O];                  // e @ b_pool
__device__ float g_A[3][(size_t)N * N];            // softmax adjacency per gate
__device__ float g_X[(size_t)N * BC];              // Xs  [m][b*C+c]
__device__ float g_Xc[(size_t)N * BC];             // candidate input, same layout
__device__ float g_Y[3][(size_t)N * BC];           // A_g @ X
__device__ float g_Wn[3][(size_t)N * KI * O];      // per-node weights E@W
__device__ float g_r[(size_t)N * B * O];           // r gate, [n][b][o]

__device__ __forceinline__ float sigmoidf_(float v) { return 1.0f / (1.0f + expf(-v)); }

// ---------------- K1: layernorm embeddings (3 gates) ----------------
__global__ void k_embed(const float* __restrict__ ne, const float* __restrict__ te,
                        const float* __restrict__ gam_z, const float* __restrict__ bet_z,
                        const float* __restrict__ gam_r, const float* __restrict__ bet_r,
                        const float* __restrict__ gam_u, const float* __restrict__ bet_u) {
    int n = blockIdx.x;
    int t = threadIdx.x;
    float v = 0.f;
    if (t < D) v = ne[n * D + t] + te[t];
    float s = v;
    #pragma unroll
    for (int off = 16; off; off >>= 1) s += __shfl_xor_sync(0xffffffffu, s, off);
    float m = s * (1.0f / D);
    float d2 = (t < D) ? (v - m) * (v - m) : 0.f;
    #pragma unroll
    for (int off = 16; off; off >>= 1) d2 += __shfl_xor_sync(0xffffffffu, d2, off);
    float rs = rsqrtf(d2 * (1.0f / D) + 1e-12f);
    if (t < D) {
        float xn = (v - m) * rs;
        g_e[0][n][t] = xn * gam_z[t] + bet_z[t];
        g_e[1][n][t] = xn * gam_r[t] + bet_r[t];
        g_e[2][n][t] = xn * gam_u[t] + bet_u[t];
    }
}

// ---------------- K2: bias = e @ b_pool ----------------
__global__ void k_bias(const float* __restrict__ bz, const float* __restrict__ br,
                       const float* __restrict__ bu) {
    int idx = blockIdx.x * blockDim.x + threadIdx.x;
    if (idx >= 3 * N * O) return;
    int o = idx % O;
    int n = (idx / O) % N;
    int g = idx / (O * N);
    const float* bp = (g == 0) ? bz : (g == 1) ? br : bu;
    float acc = 0.f;
    #pragma unroll
    for (int d = 0; d < D; d++) acc += g_e[g][n][d] * bp[d * O + o];
    g_bias[g][n][o] = acc;
}

// ---------------- K3: adjacency A = softmax(e e^T, axis=1) ----------------
__global__ void k_adj() {
    int n = blockIdx.x;
    int g = blockIdx.y;
    int t = threadIdx.x;
    __shared__ float en[D];
    __shared__ float red1[8];
    __shared__ float red2[8];
    if (t < D) en[t] = g_e[g][n][t];
    __syncthreads();

    float sv[8];
    float mx = -1e30f;
    #pragma unroll
    for (int i = 0; i < 8; i++) {
        int m = t + i * 256;
        const float4* em = (const float4*)&g_e[g][m][0];
        float4 e0 = em[0], e1 = em[1], e2 = em[2], e3 = em[3];
        float acc = en[0]*e0.x + en[1]*e0.y + en[2]*e0.z + en[3]*e0.w
                  + en[4]*e1.x + en[5]*e1.y + en[6]*e1.z + en[7]*e1.w
                  + en[8]*e2.x + en[9]*e2.y + en[10]*e2.z + en[11]*e2.w
                  + en[12]*e3.x + en[13]*e3.y + en[14]*e3.z + en[15]*e3.w;
        sv[i] = acc;
        mx = fmaxf(mx, acc);
    }
    // block max
    #pragma unroll
    for (int off = 16; off; off >>= 1) mx = fmaxf(mx, __shfl_xor_sync(0xffffffffu, mx, off));
    if ((t & 31) == 0) red1[t >> 5] = mx;
    __syncthreads();
    if (t == 0) {
        float m2 = red1[0];
        #pragma unroll
        for (int i = 1; i < 8; i++) m2 = fmaxf(m2, red1[i]);
        red1[0] = m2;
    }
    __syncthreads();
    mx = red1[0];

    float sum = 0.f;
    #pragma unroll
    for (int i = 0; i < 8; i++) { sv[i] = expf(sv[i] - mx); sum += sv[i]; }
    #pragma unroll
    for (int off = 16; off; off >>= 1) sum += __shfl_xor_sync(0xffffffffu, sum, off);
    if ((t & 31) == 0) red2[t >> 5] = sum;
    __syncthreads();
    if (t == 0) {
        float s2 = 0.f;
        #pragma unroll
        for (int i = 0; i < 8; i++) s2 += red2[i];
        red2[0] = s2;
    }
    __syncthreads();
    float inv = 1.0f / red2[0];

    float* arow = &g_A[g][(size_t)n * N];
    #pragma unroll
    for (int i = 0; i < 8; i++) arow[t + i * 256] = sv[i] * inv;
}

// ---------------- K4: build Xs [m][b*C+c] ----------------
__global__ void k_buildX(const float* __restrict__ x, const float* __restrict__ state) {
    int idx = blockIdx.x * blockDim.x + threadIdx.x;
    if (idx >= N * BC) return;
    int m = idx / BC;
    int j = idx - m * BC;
    int b = j / C;
    int c = j - b * C;
    float v = (c < DIN) ? x[(b * N + m) * DIN + c] : state[(b * N + m) * H + (c - DIN)];
    g_X[idx] = v;
}

// ---------------- K5: Wn = E @ W_pool  (M=2048, K=16, cols=8448) ----------------
__global__ void k_wn(const float* __restrict__ Wz, const float* __restrict__ Wr,
                     const float* __restrict__ Wu) {
    int g = blockIdx.z;
    const float* W = (g == 0) ? Wz : (g == 1) ? Wr : Wu;
    int ioBase = blockIdx.x * 128;
    int nBase = blockIdx.y * 64;
    __shared__ float Es[64][17];
    __shared__ float Ws[16][128];
    int t = threadIdx.x;
    {
        int r = t >> 2, d0 = (t & 3) * 4;
        #pragma unroll
        for (int i = 0; i < 4; i++) Es[r][d0 + i] = g_e[g][nBase + r][d0 + i];
    }
    {
        int d = t >> 4, c0 = (t & 15) * 8;
        const float* src = W + (size_t)d * (KI * O) + ioBase + c0;
        *(float4*)&Ws[d][c0] = *(const float4*)src;
        *(float4*)&Ws[d][c0 + 4] = *(const float4*)(src + 4);
    }
    __syncthreads();
    int ty = t >> 5, tx = t & 31;  // rows ty*8..+7, cols tx*4..+3
    float acc[8][4] = {};
    #pragma unroll
    for (int k = 0; k < 16; k++) {
        float bb[4];
        #pragma unroll
        for (int j = 0; j < 4; j++) bb[j] = Ws[k][tx * 4 + j];
        #pragma unroll
        for (int i = 0; i < 8; i++) {
            float a = Es[ty * 8 + i][k];
            #pragma unroll
            for (int j = 0; j < 4; j++) acc[i][j] += a * bb[j];
        }
    }
    #pragma unroll
    for (int i = 0; i < 8; i++) {
        float* dst = &g_Wn[g][(size_t)(nBase + ty * 8 + i) * (KI * O) + ioBase + tx * 4];
        *(float4*)dst = make_float4(acc[i][0], acc[i][1], acc[i][2], acc[i][3]);
    }
}

// ---------------- K6: SGEMM  Y[g] = A[g] @ X   (128x128x8 tiles, f32x2 FMA) ----------------
__global__ void __launch_bounds__(256, 2) k_sgemm(int gate0, int useXc) {
    int g = gate0 + blockIdx.z;
    const float* Arow = g_A[g];
    const float* X = useXc ? g_Xc : g_X;
    float* Y = g_Y[g];
    int rowBase = blockIdx.y * 128;
    int colBase = blockIdx.x * 128;
    __shared__ float As[8][128];
    __shared__ float Bs[8][128];
    int t = threadIdx.x;
    int ty = t >> 4, tx = t & 15;

    unsigned long long acc[8][4];
    #pragma unroll
    for (int i = 0; i < 8; i++)
        #pragma unroll
        for (int j = 0; j < 4; j++) acc[i][j] = 0ull;

    int ar = t >> 1;
    int ak = (t & 1) * 4;
    int br_ = t >> 5;
    int bc = (t & 31) * 4;
    const float* Aptr = Arow + (size_t)(rowBase + ar) * N + ak;
    const float* Xptr = X + (size_t)br_ * BC + colBase + bc;

    for (int k0 = 0; k0 < N; k0 += 8) {
        float4 av = *(const float4*)Aptr;
        float4 bv = *(const float4*)Xptr;
        Aptr += 8;
        Xptr += (size_t)8 * BC;
        As[ak + 0][ar] = av.x;
        As[ak + 1][ar] = av.y;
        As[ak + 2][ar] = av.z;
        As[ak + 3][ar] = av.w;
        *(float4*)&Bs[br_][bc] = bv;
        __syncthreads();
        #pragma unroll
        for (int k = 0; k < 8; k++) {
            float4 a0 = *(const float4*)&As[k][ty * 8];
            float4 a1 = *(const float4*)&As[k][ty * 8 + 4];
            ulonglong2 b01 = *(const ulonglong2*)&Bs[k][tx * 8];
            ulonglong2 b23 = *(const ulonglong2*)&Bs[k][tx * 8 + 4];
            unsigned long long bq0 = b01.x, bq1 = b01.y, bq2 = b23.x, bq3 = b23.y;
            float aa[8] = {a0.x, a0.y, a0.z, a0.w, a1.x, a1.y, a1.z, a1.w};
            #pragma unroll
            for (int i = 0; i < 8; i++) {
                unsigned long long ap;
                asm("mov.b64 %0, {%1, %1};" : "=l"(ap) : "f"(aa[i]));
                asm("fma.rn.f32x2 %0, %1, %2, %0;" : "+l"(acc[i][0]) : "l"(ap), "l"(bq0));
                asm("fma.rn.f32x2 %0, %1, %2, %0;" : "+l"(acc[i][1]) : "l"(ap), "l"(bq1));
                asm("fma.rn.f32x2 %0, %1, %2, %0;" : "+l"(acc[i][2]) : "l"(ap), "l"(bq2));
                asm("fma.rn.f32x2 %0, %1, %2, %0;" : "+l"(acc[i][3]) : "l"(ap), "l"(bq3));
            }
        }
        __syncthreads();
    }

    #pragma unroll
    for (int i = 0; i < 8; i++) {
        float out8[8];
        #pragma unroll
        for (int j = 0; j < 4; j++) {
            unsigned int lo, hi;
            asm("mov.b64 {%0, %1}, %2;" : "=r"(lo), "=r"(hi) : "l"(acc[i][j]));
            out8[2 * j] = __uint_as_float(lo);
            out8[2 * j + 1] = __uint_as_float(hi);
        }
        float* dst = Y + (size_t)(rowBase + ty * 8 + i) * BC + colBase + tx * 8;
        *(float4*)dst = make_float4(out8[0], out8[1], out8[2], out8[3]);
        *(float4*)(dst + 4) = make_float4(out8[4], out8[5], out8[6], out8[7]);
    }
}

// ---------------- K7: z/r gate apply (block = (node, gate)), builds Xc / g_r ----------------
extern __shared__ float sm_dyn[];
__global__ void k_gate_zr(const float* __restrict__ x, const float* __restrict__ state) {
    int n = blockIdx.x;
    int g = blockIdx.y;  // 0 = z, 1 = r
    float* Ws = sm_dyn;              // [KI][O]
    float* Xall = sm_dyn + KI * O;   // [B][KI]
    int t = threadIdx.x;

    const float* wsrc = &g_Wn[g][(size_t)n * KI * O];
    for (int i = t * 4; i < KI * O; i += 1024)
        *(float4*)&Ws[i] = *(const float4*)&wsrc[i];
    const float* xsrc = &g_X[(size_t)n * BC];
    const float* ysrc = &g_Y[g][(size_t)n * BC];
    for (int idx = t; idx < BC; idx += 256) {
        int b = idx / C, c = idx - b * C;
        Xall[b * KI + c] = xsrc[idx];
        Xall[b * KI + C + c] = ysrc[idx];
    }
    __syncthreads();

    int ty = t >> 4, tx = t & 15;  // b rows ty*4..+3, o cols tx*4..+3
    float acc[4][4] = {};
    #pragma unroll 4
    for (int k = 0; k < KI; k++) {
        float bb[4];
        #pragma unroll
        for (int j = 0; j < 4; j++) bb[j] = Ws[k * O + tx * 4 + j];
        #pragma unroll
        for (int i = 0; i < 4; i++) {
            float a = Xall[(ty * 4 + i) * KI + k];
            #pragma unroll
            for (int j = 0; j < 4; j++) acc[i][j] += a * bb[j];
        }
    }

    if (g == 0) {
        #pragma unroll
        for (int i = 0; i < 4; i++) {
            int b = ty * 4 + i;
            #pragma unroll
            for (int j = 0; j < 4; j++) {
                int o = tx * 4 + j;
                float z = sigmoidf_(acc[i][j] + g_bias[0][n][o]);
                float st = state[((size_t)b * N + n) * H + o];
                g_Xc[(size_t)n * BC + b * C + DIN + o] = z * st;
            }
        }
        if (t < B * DIN) {
            int b = t / DIN, c = t - b * DIN;
            g_Xc[(size_t)n * BC + b * C + c] = x[((size_t)b * N + n) * DIN + c];
        }
    } else {
        #pragma unroll
        for (int i = 0; i < 4; i++) {
            int b = ty * 4 + i;
            #pragma unroll
            for (int j = 0; j < 4; j++) {
                int o = tx * 4 + j;
                float r = sigmoidf_(acc[i][j] + g_bias[1][n][o]);
                g_r[((size_t)n * B + b) * O + o] = r;
            }
        }
    }
}

// ---------------- K8: final u gate + GRU combine ----------------
__global__ void k_final(const float* __restrict__ state, float* __restrict__ out) {
    int n = blockIdx.x;
    float* Ws = sm_dyn;
    float* Xall = sm_dyn + KI * O;
    int t = threadIdx.x;

    const float* wsrc = &g_Wn[2][(size_t)n * KI * O];
    for (int i = t * 4; i < KI * O; i += 1024)
        *(float4*)&Ws[i] = *(const float4*)&wsrc[i];
    const float* xsrc = &g_Xc[(size_t)n * BC];
    const float* ysrc = &g_Y[2][(size_t)n * BC];
    for (int idx = t; idx < BC; idx += 256) {
        int b = idx / C, c = idx - b * C;
        Xall[b * KI + c] = xsrc[idx];
        Xall[b * KI + C + c] = ysrc[idx];
    }
    __syncthreads();

    int ty = t >> 4, tx = t & 15;
    float acc[4][4] = {};
    #pragma unroll 4
    for (int k = 0; k < KI; k++) {
        float bb[4];
        #pragma unroll
        for (int j = 0; j < 4; j++) bb[j] = Ws[k * O + tx * 4 + j];
        #pragma unroll
        for (int i = 0; i < 4; i++) {
            float a = Xall[(ty * 4 + i) * KI + k];
            #pragma unroll
            for (int j = 0; j < 4; j++) acc[i][j] += a * bb[j];
        }
    }

    #pragma unroll
    for (int i = 0; i < 4; i++) {
        int b = ty * 4 + i;
        #pragma unroll
        for (int j = 0; j < 4; j++) {
            int o = tx * 4 + j;
            float hc = tanhf(acc[i][j] + g_bias[2][n][o]);
            float r = g_r[((size_t)n * B + b) * O + o];
            float st = state[((size_t)b * N + n) * H + o];
            out[((size_t)b * N + n) * O + o] = r * st + (1.0f - r) * hc;
        }
    }
}

// ---------------- launch ----------------
extern "C" void kernel_launch(void* const* d_in, const int* in_sizes, int n_in,
                              void* d_out, int out_size) {
    const float* x     = (const float*)d_in[0];
    const float* state = (const float*)d_in[1];
    const float* ne    = (const float*)d_in[2];
    const float* te    = (const float*)d_in[3];
    const float* W_z   = (const float*)d_in[4];
    const float* b_z   = (const float*)d_in[5];
    const float* gam_z = (const float*)d_in[6];
    const float* bet_z = (const float*)d_in[7];
    const float* W_r   = (const float*)d_in[8];
    const float* b_r   = (const float*)d_in[9];
    const float* gam_r = (const float*)d_in[10];
    const float* bet_r = (const float*)d_in[11];
    const float* W_u   = (const float*)d_in[12];
    const float* b_u   = (const float*)d_in[13];
    const float* gam_u = (const float*)d_in[14];
    const float* bet_u = (const float*)d_in[15];
    float* out = (float*)d_out;

    const int DYN_SMEM = (KI * O + B * KI) * 4;  // 67584 bytes
    cudaFuncSetAttribute(k_gate_zr, cudaFuncAttributeMaxDynamicSharedMemorySize, DYN_SMEM);
    cudaFuncSetAttribute(k_final, cudaFuncAttributeMaxDynamicSharedMemorySize, DYN_SMEM);

    k_embed<<<N, 32>>>(ne, te, gam_z, bet_z, gam_r, bet_r, gam_u, bet_u);
    k_bias<<<(3 * N * O + 255) / 256, 256>>>(b_z, b_r, b_u);
    k_adj<<<dim3(N, 3), 256>>>();
    k_buildX<<<(N * BC + 255) / 256, 256>>>(x, state);
    k_wn<<<dim3(66, 32, 3), 256>>>(W_z, W_r, W_u);
    k_sgemm<<<dim3(33, 16, 2), 256>>>(0, 0);           // Y_z, Y_r
    k_gate_zr<<<dim3(N, 2), 256, DYN_SMEM>>>(x, state);
    k_sgemm<<<dim3(33, 16, 1), 256>>>(2, 1);           // Y_u = A_u @ Xc
    k_final<<<N, 256, DYN_SMEM>>>(state, out);
}

// round 4
// speedup vs baseline: 1.8692x; 1.8692x over previous
#include <cuda_runtime.h>
#include <cuda_bf16.h>
#include <cstdint>
#include <math.h>

// Problem constants
#define B   64
#define N   2048
#define D   16
#define H   64
#define DIN 2
#define C   66          // DIN + H
#define KI  132         // 2*C
#define O   64
#define BC  (B*C)       // 4224

// ---------------- scratch (static __device__, no allocation) ----------------
__device__ float g_e[3][N][D];
__device__ float g_bias[3][N][O];
__device__ __align__(16) __nv_bfloat16 g_Ah[3][(size_t)N * N];    // adjacency hi (bf16)
__device__ __align__(16) __nv_bfloat16 g_Al[3][(size_t)N * N];    // adjacency lo (bf16)
__device__ float g_X[(size_t)N * BC];                              // Xs fp32 [m][col]
__device__ float g_Xc[(size_t)N * BC];                             // candidate fp32 [m][col]
__device__ __align__(16) __nv_bfloat16 g_Xth[(size_t)BC * N];     // Xs^T hi [col][m]
__device__ __align__(16) __nv_bfloat16 g_Xtl[(size_t)BC * N];     // Xs^T lo
__device__ __align__(16) __nv_bfloat16 g_Xcth[(size_t)BC * N];    // Xc^T hi
__device__ __align__(16) __nv_bfloat16 g_Xctl[(size_t)BC * N];    // Xc^T lo
__device__ float g_Y[3][(size_t)N * BC];                           // A @ X  fp32
__device__ float g_Wn[3][(size_t)N * KI * O];                      // per-node weights
__device__ float g_r[(size_t)N * B * O];

__device__ __forceinline__ float sigmoidf_(float v) { return 1.0f / (1.0f + expf(-v)); }

__device__ __forceinline__ uint32_t smem_u32(const void* p) {
    uint32_t a;
    asm("{ .reg .u64 t; cvta.to.shared.u64 t, %1; cvt.u32.u64 %0, t; }" : "=r"(a) : "l"(p));
    return a;
}

#define LDM_X4(r, addr) \
    asm volatile("ldmatrix.sync.aligned.m8n8.x4.shared.b16 {%0,%1,%2,%3}, [%4];" \
        : "=r"((r)[0]), "=r"((r)[1]), "=r"((r)[2]), "=r"((r)[3]) : "r"(addr))

#define MMA_BF16(d, a, b) \
    asm volatile("mma.sync.aligned.m16n8k16.row.col.f32.bf16.bf16.f32 " \
        "{%0,%1,%2,%3}, {%4,%5,%6,%7}, {%8,%9}, {%0,%1,%2,%3};" \
        : "+f"((d)[0]), "+f"((d)[1]), "+f"((d)[2]), "+f"((d)[3]) \
        : "r"((a)[0]), "r"((a)[1]), "r"((a)[2]), "r"((a)[3]), "r"((b)[0]), "r"((b)[1]))

// ---------------- K1: layernorm embeddings ----------------
__global__ void k_embed(const float* __restrict__ ne, const float* __restrict__ te,
                        const float* __restrict__ gam_z, const float* __restrict__ bet_z,
                        const float* __restrict__ gam_r, const float* __restrict__ bet_r,
                        const float* __restrict__ gam_u, const float* __restrict__ bet_u) {
    int n = blockIdx.x;
    int t = threadIdx.x;
    float v = 0.f;
    if (t < D) v = ne[n * D + t] + te[t];
    float s = v;
    #pragma unroll
    for (int off = 16; off; off >>= 1) s += __shfl_xor_sync(0xffffffffu, s, off);
    float m = s * (1.0f / D);
    float d2 = (t < D) ? (v - m) * (v - m) : 0.f;
    #pragma unroll
    for (int off = 16; off; off >>= 1) d2 += __shfl_xor_sync(0xffffffffu, d2, off);
    float rs = rsqrtf(d2 * (1.0f / D) + 1e-12f);
    if (t < D) {
        float xn = (v - m) * rs;
        g_e[0][n][t] = xn * gam_z[t] + bet_z[t];
        g_e[1][n][t] = xn * gam_r[t] + bet_r[t];
        g_e[2][n][t] = xn * gam_u[t] + bet_u[t];
    }
}

// ---------------- K2: bias = e @ b_pool ----------------
__global__ void k_bias(const float* __restrict__ bz, const float* __restrict__ br,
                       const float* __restrict__ bu) {
    int idx = blockIdx.x * blockDim.x + threadIdx.x;
    if (idx >= 3 * N * O) return;
    int o = idx % O;
    int n = (idx / O) % N;
    int g = idx / (O * N);
    const float* bp = (g == 0) ? bz : (g == 1) ? br : bu;
    float acc = 0.f;
    #pragma unroll
    for (int d = 0; d < D; d++) acc += g_e[g][n][d] * bp[d * O + o];
    g_bias[g][n][o] = acc;
}

// ---------------- K3: adjacency softmax -> bf16 hi/lo ----------------
__global__ void k_adj() {
    int n = blockIdx.x;
    int g = blockIdx.y;
    int t = threadIdx.x;
    __shared__ float en[D];
    __shared__ float red1[8];
    __shared__ float red2[8];
    if (t < D) en[t] = g_e[g][n][t];
    __syncthreads();

    float sv[8];
    float mx = -1e30f;
    #pragma unroll
    for (int i = 0; i < 8; i++) {
        int m = t + i * 256;
        const float4* em = (const float4*)&g_e[g][m][0];
        float4 e0 = em[0], e1 = em[1], e2 = em[2], e3 = em[3];
        float acc = en[0]*e0.x + en[1]*e0.y + en[2]*e0.z + en[3]*e0.w
                  + en[4]*e1.x + en[5]*e1.y + en[6]*e1.z + en[7]*e1.w
                  + en[8]*e2.x + en[9]*e2.y + en[10]*e2.z + en[11]*e2.w
                  + en[12]*e3.x + en[13]*e3.y + en[14]*e3.z + en[15]*e3.w;
        sv[i] = acc;
        mx = fmaxf(mx, acc);
    }
    #pragma unroll
    for (int off = 16; off; off >>= 1) mx = fmaxf(mx, __shfl_xor_sync(0xffffffffu, mx, off));
    if ((t & 31) == 0) red1[t >> 5] = mx;
    __syncthreads();
    if (t == 0) {
        float m2 = red1[0];
        #pragma unroll
        for (int i = 1; i < 8; i++) m2 = fmaxf(m2, red1[i]);
        red1[0] = m2;
    }
    __syncthreads();
    mx = red1[0];

    float sum = 0.f;
    #pragma unroll
    for (int i = 0; i < 8; i++) { sv[i] = expf(sv[i] - mx); sum += sv[i]; }
    #pragma unroll
    for (int off = 16; off; off >>= 1) sum += __shfl_xor_sync(0xffffffffu, sum, off);
    if ((t & 31) == 0) red2[t >> 5] = sum;
    __syncthreads();
    if (t == 0) {
        float s2 = 0.f;
        #pragma unroll
        for (int i = 0; i < 8; i++) s2 += red2[i];
        red2[0] = s2;
    }
    __syncthreads();
    float inv = 1.0f / red2[0];

    __nv_bfloat16* ah = &g_Ah[g][(size_t)n * N];
    __nv_bfloat16* al = &g_Al[g][(size_t)n * N];
    #pragma unroll
    for (int i = 0; i < 8; i++) {
        float a = sv[i] * inv;
        __nv_bfloat16 h = __float2bfloat16(a);
        float rem = a - __bfloat162float(h);
        ah[t + i * 256] = h;
        al[t + i * 256] = __float2bfloat16(rem);
    }
}

// ---------------- K4a: build Xs fp32 [m][col] ----------------
__global__ void k_buildX(const float* __restrict__ x, const float* __restrict__ state) {
    int idx = blockIdx.x * blockDim.x + threadIdx.x;
    if (idx >= N * BC) return;
    int m = idx / BC;
    int j = idx - m * BC;
    int b = j / C;
    int c = j - b * C;
    float v = (c < DIN) ? x[(b * N + m) * DIN + c] : state[(b * N + m) * H + (c - DIN)];
    g_X[idx] = v;
}

// ---------------- K4b: build Xs^T bf16 hi/lo [col][m] ----------------
__global__ void k_buildXt(const float* __restrict__ x, const float* __restrict__ state) {
    int idx = blockIdx.x * blockDim.x + threadIdx.x;
    if (idx >= N * BC) return;
    int col = idx / N;
    int m = idx - col * N;
    int b = col / C;
    int c = col - b * C;
    float v = (c < DIN) ? x[(b * N + m) * DIN + c] : state[(b * N + m) * H + (c - DIN)];
    __nv_bfloat16 h = __float2bfloat16(v);
    g_Xth[idx] = h;
    g_Xtl[idx] = __float2bfloat16(v - __bfloat162float(h));
}

// ---------------- K4c: build Xc^T bf16 hi/lo from g_Xc ----------------
__global__ void k_buildXct() {
    int idx = blockIdx.x * blockDim.x + threadIdx.x;
    if (idx >= N * BC) return;
    int col = idx / N;
    int m = idx - col * N;
    float v = g_Xc[(size_t)m * BC + col];
    __nv_bfloat16 h = __float2bfloat16(v);
    g_Xcth[idx] = h;
    g_Xctl[idx] = __float2bfloat16(v - __bfloat162float(h));
}

// ---------------- K5: Wn = E @ W_pool ----------------
__global__ void k_wn(const float* __restrict__ Wz, const float* __restrict__ Wr,
                     const float* __restrict__ Wu) {
    int g = blockIdx.z;
    const float* W = (g == 0) ? Wz : (g == 1) ? Wr : Wu;
    int ioBase = blockIdx.x * 128;
    int nBase = blockIdx.y * 64;
    __shared__ float Es[64][17];
    __shared__ float Ws[16][128];
    int t = threadIdx.x;
    {
        int r = t >> 2, d0 = (t & 3) * 4;
        #pragma unroll
        for (int i = 0; i < 4; i++) Es[r][d0 + i] = g_e[g][nBase + r][d0 + i];
    }
    {
        int d = t >> 4, c0 = (t & 15) * 8;
        const float* src = W + (size_t)d * (KI * O) + ioBase + c0;
        *(float4*)&Ws[d][c0] = *(const float4*)src;
        *(float4*)&Ws[d][c0 + 4] = *(const float4*)(src + 4);
    }
    __syncthreads();
    int ty = t >> 5, tx = t & 31;
    float acc[8][4] = {};
    #pragma unroll
    for (int k = 0; k < 16; k++) {
        float bb[4];
        #pragma unroll
        for (int j = 0; j < 4; j++) bb[j] = Ws[k][tx * 4 + j];
        #pragma unroll
        for (int i = 0; i < 8; i++) {
            float a = Es[ty * 8 + i][k];
            #pragma unroll
            for (int j = 0; j < 4; j++) acc[i][j] += a * bb[j];
        }
    }
    #pragma unroll
    for (int i = 0; i < 8; i++) {
        float* dst = &g_Wn[g][(size_t)(nBase + ty * 8 + i) * (KI * O) + ioBase + tx * 4];
        *(float4*)dst = make_float4(acc[i][0], acc[i][1], acc[i][2], acc[i][3]);
    }
}

// ---------------- K6: mma.sync bf16 GEMM  Y[g] = A[g] @ X  (3-term split) ----------------
// Tile 128x128, K-chunk 32. 8 warps as 4(m) x 2(n); each warp 32x64.
#define KPAD 40
__global__ void __launch_bounds__(256) k_mmagemm(int gate0, int useXc) {
    __shared__ __nv_bfloat16 sAh[128 * KPAD];
    __shared__ __nv_bfloat16 sAl[128 * KPAD];
    __shared__ __nv_bfloat16 sBh[128 * KPAD];
    __shared__ __nv_bfloat16 sBl[128 * KPAD];

    int t = threadIdx.x;
    int lane = t & 31, wid = t >> 5;
    int g = gate0 + blockIdx.z;
    const __nv_bfloat16* Ah = g_Ah[g];
    const __nv_bfloat16* Al = g_Al[g];
    const __nv_bfloat16* Bh = useXc ? g_Xcth : g_Xth;
    const __nv_bfloat16* Bl = useXc ? g_Xctl : g_Xtl;
    float* Y = g_Y[g];
    int m0 = blockIdx.y * 128;
    int c0 = blockIdx.x * 128;
    int warp_m = wid & 3;   // 0..3 -> m offset *32
    int warp_n = wid >> 2;  // 0..1 -> n offset *64

    float acc[2][8][4];
    #pragma unroll
    for (int i = 0; i < 2; i++)
        #pragma unroll
        for (int j = 0; j < 8; j++)
            #pragma unroll
            for (int q = 0; q < 4; q++) acc[i][j][q] = 0.f;

    // copy indexing: row = t/2, half = t&1 handles 16 bf16 (32B)
    int crow = t >> 1, chalf = t & 1;
    const __nv_bfloat16* gAh = Ah + (size_t)(m0 + crow) * N + chalf * 16;
    const __nv_bfloat16* gAl = Al + (size_t)(m0 + crow) * N + chalf * 16;
    const __nv_bfloat16* gBh = Bh + (size_t)(c0 + crow) * N + chalf * 16;
    const __nv_bfloat16* gBl = Bl + (size_t)(c0 + crow) * N + chalf * 16;
    int soff = crow * KPAD + chalf * 16;

    uint32_t ua_h = smem_u32(sAh), ua_l = smem_u32(sAl);
    uint32_t ub_h = smem_u32(sBh), ub_l = smem_u32(sBl);

    // per-lane ldmatrix base offsets (bytes)
    uint32_t aoff[2], boff[4];
    #pragma unroll
    for (int mt = 0; mt < 2; mt++)
        aoff[mt] = (uint32_t)(((warp_m * 32 + mt * 16 + (lane & 15)) * KPAD + ((lane >> 4) << 3)) * 2);
    #pragma unroll
    for (int p = 0; p < 4; p++)
        boff[p] = (uint32_t)(((warp_n * 64 + p * 16 + (lane & 7) + ((lane >> 4) << 3)) * KPAD + (((lane >> 3) & 1) << 3)) * 2);

    for (int kc = 0; kc < N / 32; kc++) {
        size_t ko = (size_t)kc * 32;
        uint4 vAh0 = *(const uint4*)(gAh + ko), vAh1 = *(const uint4*)(gAh + ko + 8);
        uint4 vAl0 = *(const uint4*)(gAl + ko), vAl1 = *(const uint4*)(gAl + ko + 8);
        uint4 vBh0 = *(const uint4*)(gBh + ko), vBh1 = *(const uint4*)(gBh + ko + 8);
        uint4 vBl0 = *(const uint4*)(gBl + ko), vBl1 = *(const uint4*)(gBl + ko + 8);
        __syncthreads();
        *(uint4*)(sAh + soff) = vAh0; *(uint4*)(sAh + soff + 8) = vAh1;
        *(uint4*)(sAl + soff) = vAl0; *(uint4*)(sAl + soff + 8) = vAl1;
        *(uint4*)(sBh + soff) = vBh0; *(uint4*)(sBh + soff + 8) = vBh1;
        *(uint4*)(sBl + soff) = vBl0; *(uint4*)(sBl + soff + 8) = vBl1;
        __syncthreads();

        #pragma unroll
        for (int ks = 0; ks < 2; ks++) {
            uint32_t kb = ks * 32;  // 16 elems * 2B
            uint32_t fah[2][4], fal[2][4], fbh[4][4], fbl[4][4];
            #pragma unroll
            for (int mt = 0; mt < 2; mt++) {
                LDM_X4(fah[mt], ua_h + aoff[mt] + kb);
                LDM_X4(fal[mt], ua_l + aoff[mt] + kb);
            }
            #pragma unroll
            for (int p = 0; p < 4; p++) {
                LDM_X4(fbh[p], ub_h + boff[p] + kb);
                LDM_X4(fbl[p], ub_l + boff[p] + kb);
            }
            #pragma unroll
            for (int mt = 0; mt < 2; mt++) {
                #pragma unroll
                for (int p = 0; p < 4; p++) {
                    MMA_BF16(acc[mt][2 * p],     fah[mt], &fbh[p][0]);
                    MMA_BF16(acc[mt][2 * p + 1], fah[mt], &fbh[p][2]);
                    MMA_BF16(acc[mt][2 * p],     fah[mt], &fbl[p][0]);
                    MMA_BF16(acc[mt][2 * p + 1], fah[mt], &fbl[p][2]);
                    MMA_BF16(acc[mt][2 * p],     fal[mt], &fbh[p][0]);
                    MMA_BF16(acc[mt][2 * p + 1], fal[mt], &fbh[p][2]);
                }
            }
        }
    }

    // epilogue
    #pragma unroll
    for (int mt = 0; mt < 2; mt++) {
        int r = m0 + warp_m * 32 + mt * 16 + (lane >> 2);
        #pragma unroll
        for (int nt = 0; nt < 8; nt++) {
            int cc = c0 + warp_n * 64 + nt * 8 + (lane & 3) * 2;
            float* p = Y + (size_t)r * BC + cc;
            *(float2*)p = make_float2(acc[mt][nt][0], acc[mt][nt][1]);
            *(float2*)(p + (size_t)8 * BC) = make_float2(acc[mt][nt][2], acc[mt][nt][3]);
        }
    }
}

// ---------------- K7: z/r gate apply ----------------
extern __shared__ float sm_dyn[];
__global__ void k_gate_zr(const float* __restrict__ x, const float* __restrict__ state) {
    int n = blockIdx.x;
    int g = blockIdx.y;  // 0 = z, 1 = r
    float* Ws = sm_dyn;              // [KI][O]
    float* Xall = sm_dyn + KI * O;   // [B][KI]
    int t = threadIdx.x;

    const float* wsrc = &g_Wn[g][(size_t)n * KI * O];
    for (int i = t * 4; i < KI * O; i += 1024)
        *(float4*)&Ws[i] = *(const float4*)&wsrc[i];
    const float* xsrc = &g_X[(size_t)n * BC];
    const float* ysrc = &g_Y[g][(size_t)n * BC];
    for (int idx = t; idx < BC; idx += 256) {
        int b = idx / C, c = idx - b * C;
        Xall[b * KI + c] = xsrc[idx];
        Xall[b * KI + C + c] = ysrc[idx];
    }
    __syncthreads();

    int ty = t >> 4, tx = t & 15;
    float acc[4][4] = {};
    #pragma unroll 4
    for (int k = 0; k < KI; k++) {
        float bb[4];
        #pragma unroll
        for (int j = 0; j < 4; j++) bb[j] = Ws[k * O + tx * 4 + j];
        #pragma unroll
        for (int i = 0; i < 4; i++) {
            float a = Xall[(ty * 4 + i) * KI + k];
            #pragma unroll
            for (int j = 0; j < 4; j++) acc[i][j] += a * bb[j];
        }
    }

    if (g == 0) {
        #pragma unroll
        for (int i = 0; i < 4; i++) {
            int b = ty * 4 + i;
            #pragma unroll
            for (int j = 0; j < 4; j++) {
                int o = tx * 4 + j;
                float z = sigmoidf_(acc[i][j] + g_bias[0][n][o]);
                float st = state[((size_t)b * N + n) * H + o];
                g_Xc[(size_t)n * BC + b * C + DIN + o] = z * st;
            }
        }
        if (t < B * DIN) {
            int b = t / DIN, c = t - b * DIN;
            g_Xc[(size_t)n * BC + b * C + c] = x[((size_t)b * N + n) * DIN + c];
        }
    } else {
        #pragma unroll
        for (int i = 0; i < 4; i++) {
            int b = ty * 4 + i;
            #pragma unroll
            for (int j = 0; j < 4; j++) {
                int o = tx * 4 + j;
                float r = sigmoidf_(acc[i][j] + g_bias[1][n][o]);
                g_r[((size_t)n * B + b) * O + o] = r;
            }
        }
    }
}

// ---------------- K8: final u gate + GRU combine ----------------
__global__ void k_final(const float* __restrict__ state, float* __restrict__ out) {
    int n = blockIdx.x;
    float* Ws = sm_dyn;
    float* Xall = sm_dyn + KI * O;
    int t = threadIdx.x;

    const float* wsrc = &g_Wn[2][(size_t)n * KI * O];
    for (int i = t * 4; i < KI * O; i += 1024)
        *(float4*)&Ws[i] = *(const float4*)&wsrc[i];
    const float* xsrc = &g_Xc[(size_t)n * BC];
    const float* ysrc = &g_Y[2][(size_t)n * BC];
    for (int idx = t; idx < BC; idx += 256) {
        int b = idx / C, c = idx - b * C;
        Xall[b * KI + c] = xsrc[idx];
        Xall[b * KI + C + c] = ysrc[idx];
    }
    __syncthreads();

    int ty = t >> 4, tx = t & 15;
    float acc[4][4] = {};
    #pragma unroll 4
    for (int k = 0; k < KI; k++) {
        float bb[4];
        #pragma unroll
        for (int j = 0; j < 4; j++) bb[j] = Ws[k * O + tx * 4 + j];
        #pragma unroll
        for (int i = 0; i < 4; i++) {
            float a = Xall[(ty * 4 + i) * KI + k];
            #pragma unroll
            for (int j = 0; j < 4; j++) acc[i][j] += a * bb[j];
        }
    }

    #pragma unroll
    for (int i = 0; i < 4; i++) {
        int b = ty * 4 + i;
        #pragma unroll
        for (int j = 0; j < 4; j++) {
            int o = tx * 4 + j;
            float hc = tanhf(acc[i][j] + g_bias[2][n][o]);
            float r = g_r[((size_t)n * B + b) * O + o];
            float st = state[((size_t)b * N + n) * H + o];
            out[((size_t)b * N + n) * O + o] = r * st + (1.0f - r) * hc;
        }
    }
}

// ---------------- launch ----------------
extern "C" void kernel_launch(void* const* d_in, const int* in_sizes, int n_in,
                              void* d_out, int out_size) {
    const float* x     = (const float*)d_in[0];
    const float* state = (const float*)d_in[1];
    const float* ne    = (const float*)d_in[2];
    const float* te    = (const float*)d_in[3];
    const float* W_z   = (const float*)d_in[4];
    const float* b_z   = (const float*)d_in[5];
    const float* gam_z = (const float*)d_in[6];
    const float* bet_z = (const float*)d_in[7];
    const float* W_r   = (const float*)d_in[8];
    const float* b_r   = (const float*)d_in[9];
    const float* gam_r = (const float*)d_in[10];
    const float* bet_r = (const float*)d_in[11];
    const float* W_u   = (const float*)d_in[12];
    const float* b_u   = (const float*)d_in[13];
    const float* gam_u = (const float*)d_in[14];
    const float* bet_u = (const float*)d_in[15];
    float* out = (float*)d_out;

    const int DYN_SMEM = (KI * O + B * KI) * 4;  // 67584 bytes (gate kernels)
    cudaFuncSetAttribute(k_gate_zr, cudaFuncAttributeMaxDynamicSharedMemorySize, DYN_SMEM);
    cudaFuncSetAttribute(k_final, cudaFuncAttributeMaxDynamicSharedMemorySize, DYN_SMEM);

    k_embed<<<N, 32>>>(ne, te, gam_z, bet_z, gam_r, bet_r, gam_u, bet_u);
    k_bias<<<(3 * N * O + 255) / 256, 256>>>(b_z, b_r, b_u);
    k_adj<<<dim3(N, 3), 256>>>();
    k_buildX<<<(N * BC + 255) / 256, 256>>>(x, state);
    k_buildXt<<<(N * BC + 255) / 256, 256>>>(x, state);
    k_wn<<<dim3(66, 32, 3), 256>>>(W_z, W_r, W_u);
    k_mmagemm<<<dim3(BC / 128, N / 128, 2), 256>>>(0, 0);   // Y_z, Y_r
    k_gate_zr<<<dim3(N, 2), 256, DYN_SMEM>>>(x, state);
    k_buildXct<<<(N * BC + 255) / 256, 256>>>();
    k_mmagemm<<<dim3(BC / 128, N / 128, 1), 256>>>(2, 1);   // Y_u
    k_final<<<N, 256, DYN_SMEM>>>(state, out);
}

// round 5
// speedup vs baseline: 2.1480x; 1.1492x over previous
#include <cuda_runtime.h>
#include <cuda_fp16.h>
#include <cstdint>
#include <math.h>

// Problem constants
#define B   64
#define N   2048
#define D   16
#define H   64
#define DIN 2
#define C   66          // DIN + H
#define KI  132         // 2*C
#define O   64
#define BC  (B*C)       // 4224

// ---------------- scratch (static __device__, no allocation) ----------------
__device__ float g_e[3][N][D];
__device__ float g_bias[3][N][O];
__device__ __align__(16) __half g_Af[3][(size_t)N * N];     // adjacency fp16 (single)
__device__ float g_X[(size_t)N * BC];                        // Xs fp32 [m][col]
__device__ float g_Xc[(size_t)N * BC];                       // candidate fp32 [m][col]
__device__ __align__(16) __half g_Xth[(size_t)BC * N];      // Xs^T hi [col][m]
__device__ __align__(16) __half g_Xtl[(size_t)BC * N];      // Xs^T lo
__device__ __align__(16) __half g_Xcth[(size_t)BC * N];     // Xc^T hi
__device__ __align__(16) __half g_Xctl[(size_t)BC * N];     // Xc^T lo
__device__ float g_Y[3][(size_t)N * BC];                     // A @ X  fp32
__device__ float g_Wn[3][(size_t)N * KI * O];                // per-node weights
__device__ float g_r[(size_t)N * B * O];

__device__ __forceinline__ float sigmoidf_(float v) { return 1.0f / (1.0f + expf(-v)); }

__device__ __forceinline__ uint32_t smem_u32(const void* p) {
    uint32_t a;
    asm("{ .reg .u64 t; cvta.to.shared.u64 t, %1; cvt.u32.u64 %0, t; }" : "=r"(a) : "l"(p));
    return a;
}

#define LDM_X4(r, addr) \
    asm volatile("ldmatrix.sync.aligned.m8n8.x4.shared.b16 {%0,%1,%2,%3}, [%4];" \
        : "=r"((r)[0]), "=r"((r)[1]), "=r"((r)[2]), "=r"((r)[3]) : "r"(addr))

#define MMA_F16(d, a, b) \
    asm volatile("mma.sync.aligned.m16n8k16.row.col.f32.f16.f16.f32 " \
        "{%0,%1,%2,%3}, {%4,%5,%6,%7}, {%8,%9}, {%0,%1,%2,%3};" \
        : "+f"((d)[0]), "+f"((d)[1]), "+f"((d)[2]), "+f"((d)[3]) \
        : "r"((a)[0]), "r"((a)[1]), "r"((a)[2]), "r"((a)[3]), "r"((b)[0]), "r"((b)[1]))

// ---------------- K1: layernorm embeddings ----------------
__global__ void k_embed(const float* __restrict__ ne, const float* __restrict__ te,
                        const float* __restrict__ gam_z, const float* __restrict__ bet_z,
                        const float* __restrict__ gam_r, const float* __restrict__ bet_r,
                        const float* __restrict__ gam_u, const float* __restrict__ bet_u) {
    int n = blockIdx.x;
    int t = threadIdx.x;
    float v = 0.f;
    if (t < D) v = ne[n * D + t] + te[t];
    float s = v;
    #pragma unroll
    for (int off = 16; off; off >>= 1) s += __shfl_xor_sync(0xffffffffu, s, off);
    float m = s * (1.0f / D);
    float d2 = (t < D) ? (v - m) * (v - m) : 0.f;
    #pragma unroll
    for (int off = 16; off; off >>= 1) d2 += __shfl_xor_sync(0xffffffffu, d2, off);
    float rs = rsqrtf(d2 * (1.0f / D) + 1e-12f);
    if (t < D) {
        float xn = (v - m) * rs;
        g_e[0][n][t] = xn * gam_z[t] + bet_z[t];
        g_e[1][n][t] = xn * gam_r[t] + bet_r[t];
        g_e[2][n][t] = xn * gam_u[t] + bet_u[t];
    }
}

// ---------------- K2: bias = e @ b_pool ----------------
__global__ void k_bias(const float* __restrict__ bz, const float* __restrict__ br,
                       const float* __restrict__ bu) {
    int idx = blockIdx.x * blockDim.x + threadIdx.x;
    if (idx >= 3 * N * O) return;
    int o = idx % O;
    int n = (idx / O) % N;
    int g = idx / (O * N);
    const float* bp = (g == 0) ? bz : (g == 1) ? br : bu;
    float acc = 0.f;
    #pragma unroll
    for (int d = 0; d < D; d++) acc += g_e[g][n][d] * bp[d * O + o];
    g_bias[g][n][o] = acc;
}

// ---------------- K3: adjacency softmax -> fp16 ----------------
__global__ void k_adj() {
    int n = blockIdx.x;
    int g = blockIdx.y;
    int t = threadIdx.x;
    __shared__ float en[D];
    __shared__ float red1[8];
    __shared__ float red2[8];
    if (t < D) en[t] = g_e[g][n][t];
    __syncthreads();

    float sv[8];
    float mx = -1e30f;
    #pragma unroll
    for (int i = 0; i < 8; i++) {
        int m = t + i * 256;
        const float4* em = (const float4*)&g_e[g][m][0];
        float4 e0 = em[0], e1 = em[1], e2 = em[2], e3 = em[3];
        float acc = en[0]*e0.x + en[1]*e0.y + en[2]*e0.z + en[3]*e0.w
                  + en[4]*e1.x + en[5]*e1.y + en[6]*e1.z + en[7]*e1.w
                  + en[8]*e2.x + en[9]*e2.y + en[10]*e2.z + en[11]*e2.w
                  + en[12]*e3.x + en[13]*e3.y + en[14]*e3.z + en[15]*e3.w;
        sv[i] = acc;
        mx = fmaxf(mx, acc);
    }
    #pragma unroll
    for (int off = 16; off; off >>= 1) mx = fmaxf(mx, __shfl_xor_sync(0xffffffffu, mx, off));
    if ((t & 31) == 0) red1[t >> 5] = mx;
    __syncthreads();
    if (t == 0) {
        float m2 = red1[0];
        #pragma unroll
        for (int i = 1; i < 8; i++) m2 = fmaxf(m2, red1[i]);
        red1[0] = m2;
    }
    __syncthreads();
    mx = red1[0];

    float sum = 0.f;
    #pragma unroll
    for (int i = 0; i < 8; i++) { sv[i] = expf(sv[i] - mx); sum += sv[i]; }
    #pragma unroll
    for (int off = 16; off; off >>= 1) sum += __shfl_xor_sync(0xffffffffu, sum, off);
    if ((t & 31) == 0) red2[t >> 5] = sum;
    __syncthreads();
    if (t == 0) {
        float s2 = 0.f;
        #pragma unroll
        for (int i = 0; i < 8; i++) s2 += red2[i];
        red2[0] = s2;
    }
    __syncthreads();
    float inv = 1.0f / red2[0];

    __half* af = &g_Af[g][(size_t)n * N];
    #pragma unroll
    for (int i = 0; i < 8; i++)
        af[t + i * 256] = __float2half(sv[i] * inv);
}

// ---------------- K4a: build Xs fp32 [m][col] ----------------
__global__ void k_buildX(const float* __restrict__ x, const float* __restrict__ state) {
    int idx = blockIdx.x * blockDim.x + threadIdx.x;
    if (idx >= N * BC) return;
    int m = idx / BC;
    int j = idx - m * BC;
    int b = j / C;
    int c = j - b * C;
    float v = (c < DIN) ? x[(b * N + m) * DIN + c] : state[(b * N + m) * H + (c - DIN)];
    g_X[idx] = v;
}

// ---------------- K4b: build Xs^T fp16 hi/lo [col][m] ----------------
__global__ void k_buildXt(const float* __restrict__ x, const float* __restrict__ state) {
    int idx = blockIdx.x * blockDim.x + threadIdx.x;
    if (idx >= N * BC) return;
    int col = idx / N;
    int m = idx - col * N;
    int b = col / C;
    int c = col - b * C;
    float v = (c < DIN) ? x[(b * N + m) * DIN + c] : state[(b * N + m) * H + (c - DIN)];
    __half h = __float2half(v);
    g_Xth[idx] = h;
    g_Xtl[idx] = __float2half(v - __half2float(h));
}

// ---------------- K4c: build Xc^T fp16 hi/lo from g_Xc ----------------
__global__ void k_buildXct() {
    int idx = blockIdx.x * blockDim.x + threadIdx.x;
    if (idx >= N * BC) return;
    int col = idx / N;
    int m = idx - col * N;
    float v = g_Xc[(size_t)m * BC + col];
    __half h = __float2half(v);
    g_Xcth[idx] = h;
    g_Xctl[idx] = __float2half(v - __half2float(h));
}

// ---------------- K5: Wn = E @ W_pool ----------------
__global__ void k_wn(const float* __restrict__ Wz, const float* __restrict__ Wr,
                     const float* __restrict__ Wu) {
    int g = blockIdx.z;
    const float* W = (g == 0) ? Wz : (g == 1) ? Wr : Wu;
    int ioBase = blockIdx.x * 128;
    int nBase = blockIdx.y * 64;
    __shared__ float Es[64][17];
    __shared__ float Ws[16][128];
    int t = threadIdx.x;
    {
        int r = t >> 2, d0 = (t & 3) * 4;
        #pragma unroll
        for (int i = 0; i < 4; i++) Es[r][d0 + i] = g_e[g][nBase + r][d0 + i];
    }
    {
        int d = t >> 4, c0 = (t & 15) * 8;
        const float* src = W + (size_t)d * (KI * O) + ioBase + c0;
        *(float4*)&Ws[d][c0] = *(const float4*)src;
        *(float4*)&Ws[d][c0 + 4] = *(const float4*)(src + 4);
    }
    __syncthreads();
    int ty = t >> 5, tx = t & 31;
    float acc[8][4] = {};
    #pragma unroll
    for (int k = 0; k < 16; k++) {
        float bb[4];
        #pragma unroll
        for (int j = 0; j < 4; j++) bb[j] = Ws[k][tx * 4 + j];
        #pragma unroll
        for (int i = 0; i < 8; i++) {
            float a = Es[ty * 8 + i][k];
            #pragma unroll
            for (int j = 0; j < 4; j++) acc[i][j] += a * bb[j];
        }
    }
    #pragma unroll
    for (int i = 0; i < 8; i++) {
        float* dst = &g_Wn[g][(size_t)(nBase + ty * 8 + i) * (KI * O) + ioBase + tx * 4];
        *(float4*)dst = make_float4(acc[i][0], acc[i][1], acc[i][2], acc[i][3]);
    }
}

// ---------------- K6: mma.sync fp16 GEMM  Y[g] = A[g] @ X  (A single, B hi/lo) ----------------
// Tile 128x128, K-chunk 32. 8 warps as 4(m) x 2(n); each warp 32x64.
#define KPAD 40
__global__ void __launch_bounds__(256) k_mmagemm(int gate0, int useXc) {
    __shared__ __half sA[128 * KPAD];
    __shared__ __half sBh[128 * KPAD];
    __shared__ __half sBl[128 * KPAD];

    int t = threadIdx.x;
    int lane = t & 31, wid = t >> 5;
    int g = gate0 + blockIdx.z;
    const __half* Af = g_Af[g];
    const __half* Bh = useXc ? g_Xcth : g_Xth;
    const __half* Bl = useXc ? g_Xctl : g_Xtl;
    float* Y = g_Y[g];
    int m0 = blockIdx.y * 128;
    int c0 = blockIdx.x * 128;
    int warp_m = wid & 3;   // m offset *32
    int warp_n = wid >> 2;  // n offset *64

    float acc[2][8][4];
    #pragma unroll
    for (int i = 0; i < 2; i++)
        #pragma unroll
        for (int j = 0; j < 8; j++)
            #pragma unroll
            for (int q = 0; q < 4; q++) acc[i][j][q] = 0.f;

    int crow = t >> 1, chalf = t & 1;
    const __half* gA = Af + (size_t)(m0 + crow) * N + chalf * 16;
    const __half* gBh = Bh + (size_t)(c0 + crow) * N + chalf * 16;
    const __half* gBl = Bl + (size_t)(c0 + crow) * N + chalf * 16;
    int soff = crow * KPAD + chalf * 16;

    uint32_t ua = smem_u32(sA);
    uint32_t ub_h = smem_u32(sBh);
    uint32_t ub_l = smem_u32(sBl);

    uint32_t aoff[2], boff[4];
    #pragma unroll
    for (int mt = 0; mt < 2; mt++)
        aoff[mt] = (uint32_t)(((warp_m * 32 + mt * 16 + (lane & 15)) * KPAD + ((lane >> 4) << 3)) * 2);
    #pragma unroll
    for (int p = 0; p < 4; p++)
        boff[p] = (uint32_t)(((warp_n * 64 + p * 16 + (lane & 7) + ((lane >> 4) << 3)) * KPAD + (((lane >> 3) & 1) << 3)) * 2);

    for (int kc = 0; kc < N / 32; kc++) {
        size_t ko = (size_t)kc * 32;
        uint4 vA0 = *(const uint4*)(gA + ko), vA1 = *(const uint4*)(gA + ko + 8);
        uint4 vBh0 = *(const uint4*)(gBh + ko), vBh1 = *(const uint4*)(gBh + ko + 8);
        uint4 vBl0 = *(const uint4*)(gBl + ko), vBl1 = *(const uint4*)(gBl + ko + 8);
        __syncthreads();
        *(uint4*)(sA + soff) = vA0;  *(uint4*)(sA + soff + 8) = vA1;
        *(uint4*)(sBh + soff) = vBh0; *(uint4*)(sBh + soff + 8) = vBh1;
        *(uint4*)(sBl + soff) = vBl0; *(uint4*)(sBl + soff + 8) = vBl1;
        __syncthreads();

        #pragma unroll
        for (int ks = 0; ks < 2; ks++) {
            uint32_t kb = ks * 32;  // 16 elems * 2B
            uint32_t fa[2][4], fbh[4][4], fbl[4][4];
            #pragma unroll
            for (int mt = 0; mt < 2; mt++) LDM_X4(fa[mt], ua + aoff[mt] + kb);
            #pragma unroll
            for (int p = 0; p < 4; p++) {
                LDM_X4(fbh[p], ub_h + boff[p] + kb);
                LDM_X4(fbl[p], ub_l + boff[p] + kb);
            }
            #pragma unroll
            for (int mt = 0; mt < 2; mt++) {
                #pragma unroll
                for (int p = 0; p < 4; p++) {
                    MMA_F16(acc[mt][2 * p],     fa[mt], &fbh[p][0]);
                    MMA_F16(acc[mt][2 * p + 1], fa[mt], &fbh[p][2]);
                    MMA_F16(acc[mt][2 * p],     fa[mt], &fbl[p][0]);
                    MMA_F16(acc[mt][2 * p + 1], fa[mt], &fbl[p][2]);
                }
            }
        }
    }

    // epilogue
    #pragma unroll
    for (int mt = 0; mt < 2; mt++) {
        int r = m0 + warp_m * 32 + mt * 16 + (lane >> 2);
        #pragma unroll
        for (int nt = 0; nt < 8; nt++) {
            int cc = c0 + warp_n * 64 + nt * 8 + (lane & 3) * 2;
            float* p = Y + (size_t)r * BC + cc;
            *(float2*)p = make_float2(acc[mt][nt][0], acc[mt][nt][1]);
            *(float2*)(p + (size_t)8 * BC) = make_float2(acc[mt][nt][2], acc[mt][nt][3]);
        }
    }
}

// ---------------- K7: z/r gate apply ----------------
extern __shared__ float sm_dyn[];
__global__ void k_gate_zr(const float* __restrict__ x, const float* __restrict__ state) {
    int n = blockIdx.x;
    int g = blockIdx.y;  // 0 = z, 1 = r
    float* Ws = sm_dyn;              // [KI][O]
    float* Xall = sm_dyn + KI * O;   // [B][KI]
    int t = threadIdx.x;

    const float* wsrc = &g_Wn[g][(size_t)n * KI * O];
    for (int i = t * 4; i < KI * O; i += 1024)
        *(float4*)&Ws[i] = *(const float4*)&wsrc[i];
    const float* xsrc = &g_X[(size_t)n * BC];
    const float* ysrc = &g_Y[g][(size_t)n * BC];
    for (int idx = t; idx < BC; idx += 256) {
        int b = idx / C, c = idx - b * C;
        Xall[b * KI + c] = xsrc[idx];
        Xall[b * KI + C + c] = ysrc[idx];
    }
    __syncthreads();

    int ty = t >> 4, tx = t & 15;
    float acc[4][4] = {};
    #pragma unroll 4
    for (int k = 0; k < KI; k++) {
        float4 bb = *(const float4*)&Ws[k * O + tx * 4];
        #pragma unroll
        for (int i = 0; i < 4; i++) {
            float a = Xall[(ty * 4 + i) * KI + k];
            acc[i][0] += a * bb.x;
            acc[i][1] += a * bb.y;
            acc[i][2] += a * bb.z;
            acc[i][3] += a * bb.w;
        }
    }

    if (g == 0) {
        #pragma unroll
        for (int i = 0; i < 4; i++) {
            int b = ty * 4 + i;
            #pragma unroll
            for (int j = 0; j < 4; j++) {
                int o = tx * 4 + j;
                float z = sigmoidf_(acc[i][j] + g_bias[0][n][o]);
                float st = state[((size_t)b * N + n) * H + o];
                g_Xc[(size_t)n * BC + b * C + DIN + o] = z * st;
            }
        }
        if (t < B * DIN) {
            int b = t / DIN, c = t - b * DIN;
            g_Xc[(size_t)n * BC + b * C + c] = x[((size_t)b * N + n) * DIN + c];
        }
    } else {
        #pragma unroll
        for (int i = 0; i < 4; i++) {
            int b = ty * 4 + i;
            #pragma unroll
            for (int j = 0; j < 4; j++) {
                int o = tx * 4 + j;
                float r = sigmoidf_(acc[i][j] + g_bias[1][n][o]);
                g_r[((size_t)n * B + b) * O + o] = r;
            }
        }
    }
}

// ---------------- K8: final u gate + GRU combine ----------------
__global__ void k_final(const float* __restrict__ state, float* __restrict__ out) {
    int n = blockIdx.x;
    float* Ws = sm_dyn;
    float* Xall = sm_dyn + KI * O;
    int t = threadIdx.x;

    const float* wsrc = &g_Wn[2][(size_t)n * KI * O];
    for (int i = t * 4; i < KI * O; i += 1024)
        *(float4*)&Ws[i] = *(const float4*)&wsrc[i];
    const float* xsrc = &g_Xc[(size_t)n * BC];
    const float* ysrc = &g_Y[2][(size_t)n * BC];
    for (int idx = t; idx < BC; idx += 256) {
        int b = idx / C, c = idx - b * C;
        Xall[b * KI + c] = xsrc[idx];
        Xall[b * KI + C + c] = ysrc[idx];
    }
    __syncthreads();

    int ty = t >> 4, tx = t & 15;
    float acc[4][4] = {};
    #pragma unroll 4
    for (int k = 0; k < KI; k++) {
        float4 bb = *(const float4*)&Ws[k * O + tx * 4];
        #pragma unroll
        for (int i = 0; i < 4; i++) {
            float a = Xall[(ty * 4 + i) * KI + k];
            acc[i][0] += a * bb.x;
            acc[i][1] += a * bb.y;
            acc[i][2] += a * bb.z;
            acc[i][3] += a * bb.w;
        }
    }

    #pragma unroll
    for (int i = 0; i < 4; i++) {
        int b = ty * 4 + i;
        #pragma unroll
        for (int j = 0; j < 4; j++) {
            int o = tx * 4 + j;
            float hc = tanhf(acc[i][j] + g_bias[2][n][o]);
            float r = g_r[((size_t)n * B + b) * O + o];
            float st = state[((size_t)b * N + n) * H + o];
            out[((size_t)b * N + n) * O + o] = r * st + (1.0f - r) * hc;
        }
    }
}

// ---------------- launch ----------------
extern "C" void kernel_launch(void* const* d_in, const int* in_sizes, int n_in,
                              void* d_out, int out_size) {
    const float* x     = (const float*)d_in[0];
    const float* state = (const float*)d_in[1];
    const float* ne    = (const float*)d_in[2];
    const float* te    = (const float*)d_in[3];
    const float* W_z   = (const float*)d_in[4];
    const float* b_z   = (const float*)d_in[5];
    const float* gam_z = (const float*)d_in[6];
    const float* bet_z = (const float*)d_in[7];
    const float* W_r   = (const float*)d_in[8];
    const float* b_r   = (const float*)d_in[9];
    const float* gam_r = (const float*)d_in[10];
    const float* bet_r = (const float*)d_in[11];
    const float* W_u   = (const float*)d_in[12];
    const float* b_u   = (const float*)d_in[13];
    const float* gam_u = (const float*)d_in[14];
    const float* bet_u = (const float*)d_in[15];
    float* out = (float*)d_out;

    const int DYN_SMEM = (KI * O + B * KI) * 4;  // 67584 bytes (gate kernels)
    cudaFuncSetAttribute(k_gate_zr, cudaFuncAttributeMaxDynamicSharedMemorySize, DYN_SMEM);
    cudaFuncSetAttribute(k_final, cudaFuncAttributeMaxDynamicSharedMemorySize, DYN_SMEM);

    k_embed<<<N, 32>>>(ne, te, gam_z, bet_z, gam_r, bet_r, gam_u, bet_u);
    k_bias<<<(3 * N * O + 255) / 256, 256>>>(b_z, b_r, b_u);
    k_adj<<<dim3(N, 3), 256>>>();
    k_buildX<<<(N * BC + 255) / 256, 256>>>(x, state);
    k_buildXt<<<(N * BC + 255) / 256, 256>>>(x, state);
    k_wn<<<dim3(66, 32, 3), 256>>>(W_z, W_r, W_u);
    k_mmagemm<<<dim3(BC / 128, N / 128, 2), 256>>>(0, 0);   // Y_z, Y_r
    k_gate_zr<<<dim3(N, 2), 256, DYN_SMEM>>>(x, state);
    k_buildXct<<<(N * BC + 255) / 256, 256>>>();
    k_mmagemm<<<dim3(BC / 128, N / 128, 1), 256>>>(2, 1);   // Y_u
    k_final<<<N, 256, DYN_SMEM>>>(state, out);
}

// round 6
// speedup vs baseline: 2.7568x; 1.2834x over previous
#include <cuda_runtime.h>
#include <cuda_fp16.h>
#include <cstdint>
#include <math.h>

// Problem constants
#define B   64
#define N   2048
#define D   16
#define H   64
#define DIN 2
#define C   66          // DIN + H
#define KI  132         // 2*C
#define O   64
#define BC  (B*C)       // 4224

// ---------------- scratch (static __device__, no allocation) ----------------
__device__ float g_e[3][N][D];
__device__ float g_bias[3][N][O];
__device__ __align__(16) __half g_Af[3][(size_t)N * N];     // adjacency fp16
__device__ float g_X[(size_t)N * BC];                        // Xs fp32 [m][col]
__device__ float g_Xc[(size_t)N * BC];                       // candidate fp32 [m][col]
__device__ __align__(16) __half g_Xt[(size_t)BC * N];       // Xs^T fp16 [col][m]
__device__ __align__(16) __half g_Xct[(size_t)BC * N];      // Xc^T fp16
__device__ float g_Y[3][(size_t)N * BC];                     // A @ X  fp32
__device__ float g_Wn[3][(size_t)N * KI * O];                // per-node weights
__device__ float g_r[(size_t)N * B * O];

__device__ __forceinline__ float sigmoidf_(float v) { return 1.0f / (1.0f + expf(-v)); }

__device__ __forceinline__ uint32_t smem_u32(const void* p) {
    uint32_t a;
    asm("{ .reg .u64 t; cvta.to.shared.u64 t, %1; cvt.u32.u64 %0, t; }" : "=r"(a) : "l"(p));
    return a;
}

#define LDM_X4(r, addr) \
    asm volatile("ldmatrix.sync.aligned.m8n8.x4.shared.b16 {%0,%1,%2,%3}, [%4];" \
        : "=r"((r)[0]), "=r"((r)[1]), "=r"((r)[2]), "=r"((r)[3]) : "r"(addr))

#define MMA_F16(d, a, b) \
    asm volatile("mma.sync.aligned.m16n8k16.row.col.f32.f16.f16.f32 " \
        "{%0,%1,%2,%3}, {%4,%5,%6,%7}, {%8,%9}, {%0,%1,%2,%3};" \
        : "+f"((d)[0]), "+f"((d)[1]), "+f"((d)[2]), "+f"((d)[3]) \
        : "r"((a)[0]), "r"((a)[1]), "r"((a)[2]), "r"((a)[3]), "r"((b)[0]), "r"((b)[1]))

#define CP_ASYNC16(smaddr, gptr) \
    asm volatile("cp.async.cg.shared.global [%0], [%1], 16;" :: "r"(smaddr), "l"(gptr) : "memory")
#define CP_COMMIT() asm volatile("cp.async.commit_group;" ::: "memory")
#define CP_WAIT1() asm volatile("cp.async.wait_group 1;" ::: "memory")
#define CP_WAIT0() asm volatile("cp.async.wait_group 0;" ::: "memory")

// ---------------- K1: layernorm embeddings ----------------
__global__ void k_embed(const float* __restrict__ ne, const float* __restrict__ te,
                        const float* __restrict__ gam_z, const float* __restrict__ bet_z,
                        const float* __restrict__ gam_r, const float* __restrict__ bet_r,
                        const float* __restrict__ gam_u, const float* __restrict__ bet_u) {
    int n = blockIdx.x;
    int t = threadIdx.x;
    float v = 0.f;
    if (t < D) v = ne[n * D + t] + te[t];
    float s = v;
    #pragma unroll
    for (int off = 16; off; off >>= 1) s += __shfl_xor_sync(0xffffffffu, s, off);
    float m = s * (1.0f / D);
    float d2 = (t < D) ? (v - m) * (v - m) : 0.f;
    #pragma unroll
    for (int off = 16; off; off >>= 1) d2 += __shfl_xor_sync(0xffffffffu, d2, off);
    float rs = rsqrtf(d2 * (1.0f / D) + 1e-12f);
    if (t < D) {
        float xn = (v - m) * rs;
        g_e[0][n][t] = xn * gam_z[t] + bet_z[t];
        g_e[1][n][t] = xn * gam_r[t] + bet_r[t];
        g_e[2][n][t] = xn * gam_u[t] + bet_u[t];
    }
}

// ---------------- K2: bias = e @ b_pool ----------------
__global__ void k_bias(const float* __restrict__ bz, const float* __restrict__ br,
                       const float* __restrict__ bu) {
    int idx = blockIdx.x * blockDim.x + threadIdx.x;
    if (idx >= 3 * N * O) return;
    int o = idx % O;
    int n = (idx / O) % N;
    int g = idx / (O * N);
    const float* bp = (g == 0) ? bz : (g == 1) ? br : bu;
    float acc = 0.f;
    #pragma unroll
    for (int d = 0; d < D; d++) acc += g_e[g][n][d] * bp[d * O + o];
    g_bias[g][n][o] = acc;
}

// ---------------- K3: adjacency softmax -> fp16 ----------------
__global__ void k_adj() {
    int n = blockIdx.x;
    int g = blockIdx.y;
    int t = threadIdx.x;
    __shared__ float en[D];
    __shared__ float red1[8];
    __shared__ float red2[8];
    if (t < D) en[t] = g_e[g][n][t];
    __syncthreads();

    float sv[8];
    float mx = -1e30f;
    #pragma unroll
    for (int i = 0; i < 8; i++) {
        int m = t + i * 256;
        const float4* em = (const float4*)&g_e[g][m][0];
        float4 e0 = em[0], e1 = em[1], e2 = em[2], e3 = em[3];
        float acc = en[0]*e0.x + en[1]*e0.y + en[2]*e0.z + en[3]*e0.w
                  + en[4]*e1.x + en[5]*e1.y + en[6]*e1.z + en[7]*e1.w
                  + en[8]*e2.x + en[9]*e2.y + en[10]*e2.z + en[11]*e2.w
                  + en[12]*e3.x + en[13]*e3.y + en[14]*e3.z + en[15]*e3.w;
        sv[i] = acc;
        mx = fmaxf(mx, acc);
    }
    #pragma unroll
    for (int off = 16; off; off >>= 1) mx = fmaxf(mx, __shfl_xor_sync(0xffffffffu, mx, off));
    if ((t & 31) == 0) red1[t >> 5] = mx;
    __syncthreads();
    if (t == 0) {
        float m2 = red1[0];
        #pragma unroll
        for (int i = 1; i < 8; i++) m2 = fmaxf(m2, red1[i]);
        red1[0] = m2;
    }
    __syncthreads();
    mx = red1[0];

    float sum = 0.f;
    #pragma unroll
    for (int i = 0; i < 8; i++) { sv[i] = expf(sv[i] - mx); sum += sv[i]; }
    #pragma unroll
    for (int off = 16; off; off >>= 1) sum += __shfl_xor_sync(0xffffffffu, sum, off);
    if ((t & 31) == 0) red2[t >> 5] = sum;
    __syncthreads();
    if (t == 0) {
        float s2 = 0.f;
        #pragma unroll
        for (int i = 0; i < 8; i++) s2 += red2[i];
        red2[0] = s2;
    }
    __syncthreads();
    float inv = 1.0f / red2[0];

    __half* af = &g_Af[g][(size_t)n * N];
    #pragma unroll
    for (int i = 0; i < 8; i++)
        af[t + i * 256] = __float2half(sv[i] * inv);
}

// ---------------- K4a: build Xs fp32 [m][col] ----------------
__global__ void k_buildX(const float* __restrict__ x, const float* __restrict__ state) {
    int idx = blockIdx.x * blockDim.x + threadIdx.x;
    if (idx >= N * BC) return;
    int m = idx / BC;
    int j = idx - m * BC;
    int b = j / C;
    int c = j - b * C;
    float v = (c < DIN) ? x[(b * N + m) * DIN + c] : state[(b * N + m) * H + (c - DIN)];
    g_X[idx] = v;
}

// ---------------- K4b: build Xs^T fp16 [col][m] ----------------
__global__ void k_buildXt(const float* __restrict__ x, const float* __restrict__ state) {
    int idx = blockIdx.x * blockDim.x + threadIdx.x;
    if (idx >= N * BC) return;
    int col = idx / N;
    int m = idx - col * N;
    int b = col / C;
    int c = col - b * C;
    float v = (c < DIN) ? x[(b * N + m) * DIN + c] : state[(b * N + m) * H + (c - DIN)];
    g_Xt[idx] = __float2half(v);
}

// ---------------- K4c: build Xc^T fp16 from g_Xc ----------------
__global__ void k_buildXct() {
    int idx = blockIdx.x * blockDim.x + threadIdx.x;
    if (idx >= N * BC) return;
    int col = idx / N;
    int m = idx - col * N;
    g_Xct[idx] = __float2half(g_Xc[(size_t)m * BC + col]);
}

// ---------------- K5: Wn = E @ W_pool ----------------
__global__ void k_wn(const float* __restrict__ Wz, const float* __restrict__ Wr,
                     const float* __restrict__ Wu) {
    int g = blockIdx.z;
    const float* W = (g == 0) ? Wz : (g == 1) ? Wr : Wu;
    int ioBase = blockIdx.x * 128;
    int nBase = blockIdx.y * 64;
    __shared__ float Es[64][17];
    __shared__ float Ws[16][128];
    int t = threadIdx.x;
    {
        int r = t >> 2, d0 = (t & 3) * 4;
        #pragma unroll
        for (int i = 0; i < 4; i++) Es[r][d0 + i] = g_e[g][nBase + r][d0 + i];
    }
    {
        int d = t >> 4, c0 = (t & 15) * 8;
        const float* src = W + (size_t)d * (KI * O) + ioBase + c0;
        *(float4*)&Ws[d][c0] = *(const float4*)src;
        *(float4*)&Ws[d][c0 + 4] = *(const float4*)(src + 4);
    }
    __syncthreads();
    int ty = t >> 5, tx = t & 31;
    float acc[8][4] = {};
    #pragma unroll
    for (int k = 0; k < 16; k++) {
        float bb[4];
        #pragma unroll
        for (int j = 0; j < 4; j++) bb[j] = Ws[k][tx * 4 + j];
        #pragma unroll
        for (int i = 0; i < 8; i++) {
            float a = Es[ty * 8 + i][k];
            #pragma unroll
            for (int j = 0; j < 4; j++) acc[i][j] += a * bb[j];
        }
    }
    #pragma unroll
    for (int i = 0; i < 8; i++) {
        float* dst = &g_Wn[g][(size_t)(nBase + ty * 8 + i) * (KI * O) + ioBase + tx * 4];
        *(float4*)dst = make_float4(acc[i][0], acc[i][1], acc[i][2], acc[i][3]);
    }
}

// ---------------- K6: mma.sync fp16 GEMM  Y[g] = A[g] @ X  (single term, cp.async 2-stage) ----------------
// Tile 128x128, K-chunk 32. 8 warps as 4(m) x 2(n); each warp 32x64.
#define KPAD 40
#define NCH (N / 32)
__global__ void __launch_bounds__(256) k_mmagemm(int gate0, int useXc) {
    __shared__ __half sA[2][128 * KPAD];
    __shared__ __half sB[2][128 * KPAD];

    int t = threadIdx.x;
    int lane = t & 31, wid = t >> 5;
    int g = gate0 + blockIdx.z;
    const __half* Af = g_Af[g];
    const __half* Bm = useXc ? g_Xct : g_Xt;
    float* Y = g_Y[g];
    int m0 = blockIdx.y * 128;
    int c0 = blockIdx.x * 128;
    int warp_m = wid & 3;   // m offset *32
    int warp_n = wid >> 2;  // n offset *64

    float acc[2][8][4];
    #pragma unroll
    for (int i = 0; i < 2; i++)
        #pragma unroll
        for (int j = 0; j < 8; j++)
            #pragma unroll
            for (int q = 0; q < 4; q++) acc[i][j][q] = 0.f;

    int crow = t >> 1, chalf = t & 1;
    const __half* gA = Af + (size_t)(m0 + crow) * N + chalf * 16;
    const __half* gB = Bm + (size_t)(c0 + crow) * N + chalf * 16;
    uint32_t soff_b = (uint32_t)(crow * KPAD + chalf * 16) * 2;  // bytes

    uint32_t uaS[2] = { smem_u32(sA[0]), smem_u32(sA[1]) };
    uint32_t ubS[2] = { smem_u32(sB[0]), smem_u32(sB[1]) };

    uint32_t aoff[2], boff[4];
    #pragma unroll
    for (int mt = 0; mt < 2; mt++)
        aoff[mt] = (uint32_t)(((warp_m * 32 + mt * 16 + (lane & 15)) * KPAD + ((lane >> 4) << 3)) * 2);
    #pragma unroll
    for (int p = 0; p < 4; p++)
        boff[p] = (uint32_t)(((warp_n * 64 + p * 16 + (lane & 7) + ((lane >> 4) << 3)) * KPAD + (((lane >> 3) & 1) << 3)) * 2);

    // prologue: load chunk 0 into stage 0
    {
        const __half* pa = gA;
        const __half* pb = gB;
        CP_ASYNC16(uaS[0] + soff_b, pa);
        CP_ASYNC16(uaS[0] + soff_b + 16, pa + 8);
        CP_ASYNC16(ubS[0] + soff_b, pb);
        CP_ASYNC16(ubS[0] + soff_b + 16, pb + 8);
        CP_COMMIT();
    }

    for (int kc = 0; kc < NCH; kc++) {
        int st = kc & 1;
        if (kc + 1 < NCH) {
            int sn = st ^ 1;
            const __half* pa = gA + (size_t)(kc + 1) * 32;
            const __half* pb = gB + (size_t)(kc + 1) * 32;
            CP_ASYNC16(uaS[sn] + soff_b, pa);
            CP_ASYNC16(uaS[sn] + soff_b + 16, pa + 8);
            CP_ASYNC16(ubS[sn] + soff_b, pb);
            CP_ASYNC16(ubS[sn] + soff_b + 16, pb + 8);
            CP_COMMIT();
            CP_WAIT1();
        } else {
            CP_WAIT0();
        }
        __syncthreads();

        uint32_t ua = uaS[st], ub = ubS[st];
        #pragma unroll
        for (int ks = 0; ks < 2; ks++) {
            uint32_t kb = ks * 32;  // 16 elems * 2B
            uint32_t fa[2][4], fb[4][4];
            #pragma unroll
            for (int mt = 0; mt < 2; mt++) LDM_X4(fa[mt], ua + aoff[mt] + kb);
            #pragma unroll
            for (int p = 0; p < 4; p++) LDM_X4(fb[p], ub + boff[p] + kb);
            #pragma unroll
            for (int mt = 0; mt < 2; mt++) {
                #pragma unroll
                for (int p = 0; p < 4; p++) {
                    MMA_F16(acc[mt][2 * p],     fa[mt], &fb[p][0]);
                    MMA_F16(acc[mt][2 * p + 1], fa[mt], &fb[p][2]);
                }
            }
        }
        __syncthreads();
    }

    // epilogue
    #pragma unroll
    for (int mt = 0; mt < 2; mt++) {
        int r = m0 + warp_m * 32 + mt * 16 + (lane >> 2);
        #pragma unroll
        for (int nt = 0; nt < 8; nt++) {
            int cc = c0 + warp_n * 64 + nt * 8 + (lane & 3) * 2;
            float* p = Y + (size_t)r * BC + cc;
            *(float2*)p = make_float2(acc[mt][nt][0], acc[mt][nt][1]);
            *(float2*)(p + (size_t)8 * BC) = make_float2(acc[mt][nt][2], acc[mt][nt][3]);
        }
    }
}

// ---------------- K7: z/r gate apply ----------------
extern __shared__ float sm_dyn[];
__global__ void k_gate_zr(const float* __restrict__ x, const float* __restrict__ state) {
    int n = blockIdx.x;
    int g = blockIdx.y;  // 0 = z, 1 = r
    float* Ws = sm_dyn;              // [KI][O]
    float* Xall = sm_dyn + KI * O;   // [B][KI]
    int t = threadIdx.x;

    const float* wsrc = &g_Wn[g][(size_t)n * KI * O];
    for (int i = t * 4; i < KI * O; i += 1024)
        *(float4*)&Ws[i] = *(const float4*)&wsrc[i];
    const float* xsrc = &g_X[(size_t)n * BC];
    const float* ysrc = &g_Y[g][(size_t)n * BC];
    for (int idx = t; idx < BC; idx += 256) {
        int b = idx / C, c = idx - b * C;
        Xall[b * KI + c] = xsrc[idx];
        Xall[b * KI + C + c] = ysrc[idx];
    }
    __syncthreads();

    int ty = t >> 4, tx = t & 15;
    float acc[4][4] = {};
    #pragma unroll 4
    for (int k = 0; k < KI; k++) {
        float4 bb = *(const float4*)&Ws[k * O + tx * 4];
        #pragma unroll
        for (int i = 0; i < 4; i++) {
            float a = Xall[(ty * 4 + i) * KI + k];
            acc[i][0] += a * bb.x;
            acc[i][1] += a * bb.y;
            acc[i][2] += a * bb.z;
            acc[i][3] += a * bb.w;
        }
    }

    if (g == 0) {
        #pragma unroll
        for (int i = 0; i < 4; i++) {
            int b = ty * 4 + i;
            #pragma unroll
            for (int j = 0; j < 4; j++) {
                int o = tx * 4 + j;
                float z = sigmoidf_(acc[i][j] + g_bias[0][n][o]);
                float st = state[((size_t)b * N + n) * H + o];
                g_Xc[(size_t)n * BC + b * C + DIN + o] = z * st;
            }
        }
        if (t < B * DIN) {
            int b = t / DIN, c = t - b * DIN;
            g_Xc[(size_t)n * BC + b * C + c] = x[((size_t)b * N + n) * DIN + c];
        }
    } else {
        #pragma unroll
        for (int i = 0; i < 4; i++) {
            int b = ty * 4 + i;
            #pragma unroll
            for (int j = 0; j < 4; j++) {
                int o = tx * 4 + j;
                float r = sigmoidf_(acc[i][j] + g_bias[1][n][o]);
                g_r[((size_t)n * B + b) * O + o] = r;
            }
        }
    }
}

// ---------------- K8: final u gate + GRU combine ----------------
__global__ void k_final(const float* __restrict__ state, float* __restrict__ out) {
    int n = blockIdx.x;
    float* Ws = sm_dyn;
    float* Xall = sm_dyn + KI * O;
    int t = threadIdx.x;

    const float* wsrc = &g_Wn[2][(size_t)n * KI * O];
    for (int i = t * 4; i < KI * O; i += 1024)
        *(float4*)&Ws[i] = *(const float4*)&wsrc[i];
    const float* xsrc = &g_Xc[(size_t)n * BC];
    const float* ysrc = &g_Y[2][(size_t)n * BC];
    for (int idx = t; idx < BC; idx += 256) {
        int b = idx / C, c = idx - b * C;
        Xall[b * KI + c] = xsrc[idx];
        Xall[b * KI + C + c] = ysrc[idx];
    }
    __syncthreads();

    int ty = t >> 4, tx = t & 15;
    float acc[4][4] = {};
    #pragma unroll 4
    for (int k = 0; k < KI; k++) {
        float4 bb = *(const float4*)&Ws[k * O + tx * 4];
        #pragma unroll
        for (int i = 0; i < 4; i++) {
            float a = Xall[(ty * 4 + i) * KI + k];
            acc[i][0] += a * bb.x;
            acc[i][1] += a * bb.y;
            acc[i][2] += a * bb.z;
            acc[i][3] += a * bb.w;
        }
    }

    #pragma unroll
    for (int i = 0; i < 4; i++) {
        int b = ty * 4 + i;
        #pragma unroll
        for (int j = 0; j < 4; j++) {
            int o = tx * 4 + j;
            float hc = tanhf(acc[i][j] + g_bias[2][n][o]);
            float r = g_r[((size_t)n * B + b) * O + o];
            float st = state[((size_t)b * N + n) * H + o];
            out[((size_t)b * N + n) * O + o] = r * st + (1.0f - r) * hc;
        }
    }
}

// ---------------- launch ----------------
extern "C" void kernel_launch(void* const* d_in, const int* in_sizes, int n_in,
                              void* d_out, int out_size) {
    const float* x     = (const float*)d_in[0];
    const float* state = (const float*)d_in[1];
    const float* ne    = (const float*)d_in[2];
    const float* te    = (const float*)d_in[3];
    const float* W_z   = (const float*)d_in[4];
    const float* b_z   = (const float*)d_in[5];
    const float* gam_z = (const float*)d_in[6];
    const float* bet_z = (const float*)d_in[7];
    const float* W_r   = (const float*)d_in[8];
    const float* b_r   = (const float*)d_in[9];
    const float* gam_r = (const float*)d_in[10];
    const float* bet_r = (const float*)d_in[11];
    const float* W_u   = (const float*)d_in[12];
    const float* b_u   = (const float*)d_in[13];
    const float* gam_u = (const float*)d_in[14];
    const float* bet_u = (const float*)d_in[15];
    float* out = (float*)d_out;

    const int DYN_SMEM = (KI * O + B * KI) * 4;  // 67584 bytes (gate kernels)
    cudaFuncSetAttribute(k_gate_zr, cudaFuncAttributeMaxDynamicSharedMemorySize, DYN_SMEM);
    cudaFuncSetAttribute(k_final, cudaFuncAttributeMaxDynamicSharedMemorySize, DYN_SMEM);

    k_embed<<<N, 32>>>(ne, te, gam_z, bet_z, gam_r, bet_r, gam_u, bet_u);
    k_bias<<<(3 * N * O + 255) / 256, 256>>>(b_z, b_r, b_u);
    k_adj<<<dim3(N, 3), 256>>>();
    k_buildX<<<(N * BC + 255) / 256, 256>>>(x, state);
    k_buildXt<<<(N * BC + 255) / 256, 256>>>(x, state);
    k_wn<<<dim3(66, 32, 3), 256>>>(W_z, W_r, W_u);
    k_mmagemm<<<dim3(BC / 128, N / 128, 2), 256>>>(0, 0);   // Y_z, Y_r
    k_gate_zr<<<dim3(N, 2), 256, DYN_SMEM>>>(x, state);
    k_buildXct<<<(N * BC + 255) / 256, 256>>>();
    k_mmagemm<<<dim3(BC / 128, N / 128, 1), 256>>>(2, 1);   // Y_u
    k_final<<<N, 256, DYN_SMEM>>>(state, out);
}

// round 7
// speedup vs baseline: 4.4751x; 1.6233x over previous
#include <cuda_runtime.h>
#include <cuda_fp16.h>
#include <cstdint>
#include <math.h>

// Problem constants
#define B   64
#define N   2048
#define D   16
#define H   64
#define DIN 2
#define C   66          // DIN + H
#define KI  132         // 2*C
#define O   64
#define BC  (B*C)       // 4224

// ---------------- scratch (static __device__, no allocation) ----------------
__device__ int   g_same[2];                                   // [0]: r==z params, [1]: u==z params
__device__ float g_e[3][N][D];
__device__ float g_bias[3][N][O];
__device__ __align__(16) __half g_Af[3][(size_t)N * N];       // adjacency fp16 [m][k]
__device__ __align__(16) __half g_Xh[(size_t)N * BC];         // Xs fp16 [m][col]
__device__ __align__(16) __half g_Xch[(size_t)N * BC];        // Xc fp16 [m][col]
__device__ __align__(16) __half g_Yh[3][(size_t)N * BC];      // A @ X fp16
__device__ __align__(16) __half g_Wnh[3][(size_t)N * KI * O]; // per-node weights fp16
__device__ float g_r[(size_t)N * B * O];

__device__ __forceinline__ float sigmoidf_(float v) { return 1.0f / (1.0f + expf(-v)); }

__device__ __forceinline__ uint32_t smem_u32(const void* p) {
    uint32_t a;
    asm("{ .reg .u64 t; cvta.to.shared.u64 t, %1; cvt.u32.u64 %0, t; }" : "=r"(a) : "l"(p));
    return a;
}

#define LDM_X4(r, addr) \
    asm volatile("ldmatrix.sync.aligned.m8n8.x4.shared.b16 {%0,%1,%2,%3}, [%4];" \
        : "=r"((r)[0]), "=r"((r)[1]), "=r"((r)[2]), "=r"((r)[3]) : "r"(addr))
#define LDM_X4_T(r, addr) \
    asm volatile("ldmatrix.sync.aligned.m8n8.x4.trans.shared.b16 {%0,%1,%2,%3}, [%4];" \
        : "=r"((r)[0]), "=r"((r)[1]), "=r"((r)[2]), "=r"((r)[3]) : "r"(addr))

#define MMA_F16(d, a, b) \
    asm volatile("mma.sync.aligned.m16n8k16.row.col.f32.f16.f16.f32 " \
        "{%0,%1,%2,%3}, {%4,%5,%6,%7}, {%8,%9}, {%0,%1,%2,%3};" \
        : "+f"((d)[0]), "+f"((d)[1]), "+f"((d)[2]), "+f"((d)[3]) \
        : "r"((a)[0]), "r"((a)[1]), "r"((a)[2]), "r"((a)[3]), "r"((b)[0]), "r"((b)[1]))

#define CP_ASYNC16(smaddr, gptr) \
    asm volatile("cp.async.cg.shared.global [%0], [%1], 16;" :: "r"(smaddr), "l"(gptr) : "memory")
#define CP_COMMIT() asm volatile("cp.async.commit_group;" ::: "memory")
#define CP_WAIT1() asm volatile("cp.async.wait_group 1;" ::: "memory")
#define CP_WAIT0() asm volatile("cp.async.wait_group 0;" ::: "memory")

// ---------------- K0: runtime equality flags for gate params ----------------
__global__ void k_flags(const float* gz, const float* bz, const float* gr, const float* br,
                        const float* gu, const float* bu) {
    int t = threadIdx.x;
    bool okr = true, oku = true;
    if (t < D) {
        okr = (gr[t] == gz[t]) && (br[t] == bz[t]);
        oku = (gu[t] == gz[t]) && (bu[t] == bz[t]);
    }
    unsigned mr = __ballot_sync(0xffffffffu, okr);
    unsigned mu = __ballot_sync(0xffffffffu, oku);
    if (t == 0) { g_same[0] = (mr == 0xffffffffu); g_same[1] = (mu == 0xffffffffu); }
}

// ---------------- K1: layernorm embeddings ----------------
__global__ void k_embed(const float* __restrict__ ne, const float* __restrict__ te,
                        const float* __restrict__ gam_z, const float* __restrict__ bet_z,
                        const float* __restrict__ gam_r, const float* __restrict__ bet_r,
                        const float* __restrict__ gam_u, const float* __restrict__ bet_u) {
    int n = blockIdx.x;
    int t = threadIdx.x;
    float v = 0.f;
    if (t < D) v = ne[n * D + t] + te[t];
    float s = v;
    #pragma unroll
    for (int off = 16; off; off >>= 1) s += __shfl_xor_sync(0xffffffffu, s, off);
    float m = s * (1.0f / D);
    float d2 = (t < D) ? (v - m) * (v - m) : 0.f;
    #pragma unroll
    for (int off = 16; off; off >>= 1) d2 += __shfl_xor_sync(0xffffffffu, d2, off);
    float rs = rsqrtf(d2 * (1.0f / D) + 1e-12f);
    if (t < D) {
        float xn = (v - m) * rs;
        g_e[0][n][t] = xn * gam_z[t] + bet_z[t];
        g_e[1][n][t] = xn * gam_r[t] + bet_r[t];
        g_e[2][n][t] = xn * gam_u[t] + bet_u[t];
    }
}

// ---------------- K2: bias = e @ b_pool ----------------
__global__ void k_bias(const float* __restrict__ bz, const float* __restrict__ br,
                       const float* __restrict__ bu) {
    int idx = blockIdx.x * blockDim.x + threadIdx.x;
    if (idx >= 3 * N * O) return;
    int o = idx % O;
    int n = (idx / O) % N;
    int g = idx / (O * N);
    const float* bp = (g == 0) ? bz : (g == 1) ? br : bu;
    float acc = 0.f;
    #pragma unroll
    for (int d = 0; d < D; d++) acc += g_e[g][n][d] * bp[d * O + o];
    g_bias[g][n][o] = acc;
}

// ---------------- K3: adjacency softmax -> fp16 (4 rows/block, skip dup gates) ----------------
__global__ void __launch_bounds__(256) k_adj() {
    int g = blockIdx.y;
    if (g > 0 && g_same[g - 1]) return;
    int n0 = blockIdx.x * 4;
    int t = threadIdx.x, lane = t & 31, w = t >> 5;
    __shared__ float er[4][16];
    __shared__ float redA[4][8];
    __shared__ float finM[4], finS[4];
    if (t < 64) er[t >> 4][t & 15] = g_e[g][n0 + (t >> 4)][t & 15];
    __syncthreads();

    float dots[4][8];
    float mx[4] = {-1e30f, -1e30f, -1e30f, -1e30f};
    #pragma unroll
    for (int i = 0; i < 8; i++) {
        int col = t + i * 256;
        const float4* em = (const float4*)&g_e[g][col][0];
        float4 e0 = em[0], e1 = em[1], e2 = em[2], e3 = em[3];
        float ec[16] = {e0.x, e0.y, e0.z, e0.w, e1.x, e1.y, e1.z, e1.w,
                        e2.x, e2.y, e2.z, e2.w, e3.x, e3.y, e3.z, e3.w};
        #pragma unroll
        for (int r = 0; r < 4; r++) {
            float d = 0.f;
            #pragma unroll
            for (int k = 0; k < 16; k++) d += er[r][k] * ec[k];
            dots[r][i] = d;
            mx[r] = fmaxf(mx[r], d);
        }
    }
    // block max per row
    #pragma unroll
    for (int r = 0; r < 4; r++) {
        float m = mx[r];
        #pragma unroll
        for (int off = 16; off; off >>= 1) m = fmaxf(m, __shfl_xor_sync(0xffffffffu, m, off));
        if (lane == 0) redA[r][w] = m;
    }
    __syncthreads();
    if (t < 4) {
        float M = redA[t][0];
        #pragma unroll
        for (int j = 1; j < 8; j++) M = fmaxf(M, redA[t][j]);
        finM[t] = M;
    }
    __syncthreads();
    // exp + block sum per row
    #pragma unroll
    for (int r = 0; r < 4; r++) {
        float M = finM[r];
        float s = 0.f;
        #pragma unroll
        for (int i = 0; i < 8; i++) { dots[r][i] = __expf(dots[r][i] - M); s += dots[r][i]; }
        #pragma unroll
        for (int off = 16; off; off >>= 1) s += __shfl_xor_sync(0xffffffffu, s, off);
        if (lane == 0) redA[r][w] = s;
    }
    __syncthreads();
    if (t < 4) {
        float S = 0.f;
        #pragma unroll
        for (int j = 0; j < 8; j++) S += redA[t][j];
        finS[t] = 1.0f / S;
    }
    __syncthreads();
    #pragma unroll
    for (int r = 0; r < 4; r++) {
        float inv = finS[r];
        __half* out = &g_Af[g][(size_t)(n0 + r) * N];
        #pragma unroll
        for (int i = 0; i < 8; i++) out[t + i * 256] = __float2half(dots[r][i] * inv);
    }
}

// ---------------- K4: build Xs fp16 [m][col] ----------------
__global__ void k_buildXh(const float* __restrict__ x, const float* __restrict__ state) {
    int idx = blockIdx.x * blockDim.x + threadIdx.x;
    if (idx >= N * BC) return;
    int m = idx / BC;
    int j = idx - m * BC;
    int b = j / C;
    int c = j - b * C;
    float v = (c < DIN) ? x[(b * N + m) * DIN + c] : state[(b * N + m) * H + (c - DIN)];
    g_Xh[idx] = __float2half(v);
}

// ---------------- K5: Wn = E @ W_pool -> fp16 ----------------
__global__ void k_wn(const float* __restrict__ Wz, const float* __restrict__ Wr,
                     const float* __restrict__ Wu) {
    int g = blockIdx.z;
    const float* W = (g == 0) ? Wz : (g == 1) ? Wr : Wu;
    int ioBase = blockIdx.x * 128;
    int nBase = blockIdx.y * 64;
    __shared__ float Es[64][17];
    __shared__ float Ws[16][128];
    int t = threadIdx.x;
    {
        int r = t >> 2, d0 = (t & 3) * 4;
        #pragma unroll
        for (int i = 0; i < 4; i++) Es[r][d0 + i] = g_e[g][nBase + r][d0 + i];
    }
    {
        int d = t >> 4, c0 = (t & 15) * 8;
        const float* src = W + (size_t)d * (KI * O) + ioBase + c0;
        *(float4*)&Ws[d][c0] = *(const float4*)src;
        *(float4*)&Ws[d][c0 + 4] = *(const float4*)(src + 4);
    }
    __syncthreads();
    int ty = t >> 5, tx = t & 31;
    float acc[8][4] = {};
    #pragma unroll
    for (int k = 0; k < 16; k++) {
        float bb[4];
        #pragma unroll
        for (int j = 0; j < 4; j++) bb[j] = Ws[k][tx * 4 + j];
        #pragma unroll
        for (int i = 0; i < 8; i++) {
            float a = Es[ty * 8 + i][k];
            #pragma unroll
            for (int j = 0; j < 4; j++) acc[i][j] += a * bb[j];
        }
    }
    #pragma unroll
    for (int i = 0; i < 8; i++) {
        __half2* dst = (__half2*)&g_Wnh[g][(size_t)(nBase + ty * 8 + i) * (KI * O) + ioBase + tx * 4];
        dst[0] = __floats2half2_rn(acc[i][0], acc[i][1]);
        dst[1] = __floats2half2_rn(acc[i][2], acc[i][3]);
    }
}

// ---------------- K6: mma.sync fp16 GEMM  Y = A @ X  (B via ldmatrix.trans, 3-stage cp.async) ----------------
#define APAD 40
#define BPAD 136
#define STG_A (128 * APAD)   // halves
#define STG_B (32 * BPAD)    // halves
#define STG   (STG_A + STG_B)
#define NCH   (N / 32)
#define GEMM_SMEM (3 * STG * 2)

__global__ void __launch_bounds__(256) k_mmagemm(int gate0, int useXc) {
    extern __shared__ __half gsm[];
    int t = threadIdx.x, lane = t & 31, wid = t >> 5;

    const __half* Aptr;
    __half* Yout;
    if (gate0 == 2) {
        Aptr = g_same[1] ? g_Af[0] : g_Af[2];
        Yout = g_Yh[2];
    } else {
        int gate = blockIdx.z;
        if (gate == 1 && g_same[0]) return;   // Y_r identical to Y_z
        Aptr = g_Af[gate];
        Yout = g_Yh[gate];
    }
    const __half* Bptr = useXc ? g_Xch : g_Xh;

    int m0 = blockIdx.y * 128, c0 = blockIdx.x * 128;
    int warp_m = wid & 3, warp_n = wid >> 2;

    float acc[2][8][4];
    #pragma unroll
    for (int i = 0; i < 2; i++)
        #pragma unroll
        for (int j = 0; j < 8; j++)
            #pragma unroll
            for (int q = 0; q < 4; q++) acc[i][j][q] = 0.f;

    // cp.async assignments
    int arow = t >> 1, aseg = t & 1;     // A: 128 rows x 64B, 32B per thread
    const __half* gA = Aptr + (size_t)(m0 + arow) * N + aseg * 16;
    uint32_t sAoff = (uint32_t)(arow * APAD + aseg * 16) * 2;
    int brow = t >> 3, bseg = t & 7;     // B: 32 rows x 256B, 32B per thread
    const __half* gB = Bptr + c0 + bseg * 16;
    uint32_t sBoff = (uint32_t)(brow * BPAD + bseg * 16) * 2;

    uint32_t base = smem_u32(gsm);

    // ldmatrix lane offsets
    uint32_t aoff[2], boff[4];
    #pragma unroll
    for (int mt = 0; mt < 2; mt++)
        aoff[mt] = (uint32_t)(((warp_m * 32 + mt * 16 + (lane & 15)) * APAD + ((lane >> 4) << 3)) * 2);
    #pragma unroll
    for (int p = 0; p < 4; p++)
        boff[p] = (uint32_t)(((lane & 15) * BPAD + warp_n * 64 + p * 16 + ((lane >> 4) << 3)) * 2);

    #define ISSUE(kc, s) do { \
        const __half* pa = gA + (size_t)(kc) * 32; \
        const __half* pb = gB + (size_t)((kc) * 32 + brow) * BC; \
        uint32_t da = base + (s) * (STG * 2) + sAoff; \
        uint32_t db = base + (s) * (STG * 2) + STG_A * 2 + sBoff; \
        CP_ASYNC16(da, pa); CP_ASYNC16(da + 16, pa + 8); \
        CP_ASYNC16(db, pb); CP_ASYNC16(db + 16, pb + 8); \
        CP_COMMIT(); \
    } while (0)

    ISSUE(0, 0);
    ISSUE(1, 1);

    for (int kc = 0; kc < NCH; kc++) {
        int st = kc % 3;
        if (kc == NCH - 1) { CP_WAIT0(); } else { CP_WAIT1(); }
        __syncthreads();
        if (kc + 2 < NCH) ISSUE(kc + 2, (kc + 2) % 3);

        uint32_t ua = base + st * (STG * 2);
        uint32_t ub = ua + STG_A * 2;
        #pragma unroll
        for (int ks = 0; ks < 2; ks++) {
            uint32_t fa[2][4], fb[4][4];
            #pragma unroll
            for (int mt = 0; mt < 2; mt++) LDM_X4(fa[mt], ua + aoff[mt] + ks * 32);
            #pragma unroll
            for (int p = 0; p < 4; p++) LDM_X4_T(fb[p], ub + boff[p] + ks * 16 * BPAD * 2);
            #pragma unroll
            for (int mt = 0; mt < 2; mt++) {
                #pragma unroll
                for (int p = 0; p < 4; p++) {
                    MMA_F16(acc[mt][2 * p],     fa[mt], &fb[p][0]);
                    MMA_F16(acc[mt][2 * p + 1], fa[mt], &fb[p][2]);
                }
            }
        }
    }
    #undef ISSUE

    // epilogue -> fp16
    #pragma unroll
    for (int mt = 0; mt < 2; mt++) {
        int r = m0 + warp_m * 32 + mt * 16 + (lane >> 2);
        #pragma unroll
        for (int nt = 0; nt < 8; nt++) {
            int cc = c0 + warp_n * 64 + nt * 8 + (lane & 3) * 2;
            *(__half2*)&Yout[(size_t)r * BC + cc] = __floats2half2_rn(acc[mt][nt][0], acc[mt][nt][1]);
            *(__half2*)&Yout[(size_t)(r + 8) * BC + cc] = __floats2half2_rn(acc[mt][nt][2], acc[mt][nt][3]);
        }
    }
}

// ---------------- K7: z/r gate apply ----------------
#define GATE_SMEM (KI * O * 2 + B * KI * 4)   // 50688 bytes
__global__ void k_gate_zr(const float* __restrict__ x, const float* __restrict__ state) {
    extern __shared__ char smraw[];
    __half* Wh = (__half*)smraw;
    float* Xall = (float*)(smraw + KI * O * 2);
    int n = blockIdx.x;
    int g = blockIdx.y;  // 0 = z, 1 = r
    int t = threadIdx.x;

    const __half* wsrc = g_Wnh[g] + (size_t)n * KI * O;
    for (int i = t * 8; i < KI * O; i += 2048)
        *(uint4*)&Wh[i] = *(const uint4*)&wsrc[i];
    const __half* xsrc = g_Xh + (size_t)n * BC;
    const __half* ysrc = ((g == 1) && g_same[0]) ? (g_Yh[0] + (size_t)n * BC)
                                                 : (g_Yh[g] + (size_t)n * BC);
    for (int idx = t; idx < BC; idx += 256) {
        int b = idx / C, c = idx - b * C;
        Xall[b * KI + c] = __half2float(xsrc[idx]);
        Xall[b * KI + C + c] = __half2float(ysrc[idx]);
    }
    __syncthreads();

    int ty = t >> 4, tx = t & 15;
    float acc[4][4] = {};
    #pragma unroll 4
    for (int k = 0; k < KI; k++) {
        const __half2* wp = (const __half2*)&Wh[k * O + tx * 4];
        float2 f0 = __half22float2(wp[0]);
        float2 f1 = __half22float2(wp[1]);
        #pragma unroll
        for (int i = 0; i < 4; i++) {
            float a = Xall[(ty * 4 + i) * KI + k];
            acc[i][0] += a * f0.x;
            acc[i][1] += a * f0.y;
            acc[i][2] += a * f1.x;
            acc[i][3] += a * f1.y;
        }
    }

    if (g == 0) {
        #pragma unroll
        for (int i = 0; i < 4; i++) {
            int b = ty * 4 + i;
            #pragma unroll
            for (int j = 0; j < 4; j++) {
                int o = tx * 4 + j;
                float z = sigmoidf_(acc[i][j] + g_bias[0][n][o]);
                float st = state[((size_t)b * N + n) * H + o];
                g_Xch[(size_t)n * BC + b * C + DIN + o] = __float2half(z * st);
            }
        }
        if (t < B * DIN) {
            int b = t / DIN, c = t - b * DIN;
            g_Xch[(size_t)n * BC + b * C + c] = __float2half(x[((size_t)b * N + n) * DIN + c]);
        }
    } else {
        #pragma unroll
        for (int i = 0; i < 4; i++) {
            int b = ty * 4 + i;
            #pragma unroll
            for (int j = 0; j < 4; j++) {
                int o = tx * 4 + j;
                float r = sigmoidf_(acc[i][j] + g_bias[1][n][o]);
                g_r[((size_t)n * B + b) * O + o] = r;
            }
        }
    }
}

// ---------------- K8: final u gate + GRU combine ----------------
__global__ void k_final(const float* __restrict__ state, float* __restrict__ out) {
    extern __shared__ char smraw[];
    __half* Wh = (__half*)smraw;
    float* Xall = (float*)(smraw + KI * O * 2);
    int n = blockIdx.x;
    int t = threadIdx.x;

    const __half* wsrc = g_Wnh[2] + (size_t)n * KI * O;
    for (int i = t * 8; i < KI * O; i += 2048)
        *(uint4*)&Wh[i] = *(const uint4*)&wsrc[i];
    const __half* xsrc = g_Xch + (size_t)n * BC;
    const __half* ysrc = g_Yh[2] + (size_t)n * BC;
    for (int idx = t; idx < BC; idx += 256) {
        int b = idx / C, c = idx - b * C;
        Xall[b * KI + c] = __half2float(xsrc[idx]);
        Xall[b * KI + C + c] = __half2float(ysrc[idx]);
    }
    __syncthreads();

    int ty = t >> 4, tx = t & 15;
    float acc[4][4] = {};
    #pragma unroll 4
    for (int k = 0; k < KI; k++) {
        const __half2* wp = (const __half2*)&Wh[k * O + tx * 4];
        float2 f0 = __half22float2(wp[0]);
        float2 f1 = __half22float2(wp[1]);
        #pragma unroll
        for (int i = 0; i < 4; i++) {
            float a = Xall[(ty * 4 + i) * KI + k];
            acc[i][0] += a * f0.x;
            acc[i][1] += a * f0.y;
            acc[i][2] += a * f1.x;
            acc[i][3] += a * f1.y;
        }
    }

    #pragma unroll
    for (int i = 0; i < 4; i++) {
        int b = ty * 4 + i;
        #pragma unroll
        for (int j = 0; j < 4; j++) {
            int o = tx * 4 + j;
            float hc = tanhf(acc[i][j] + g_bias[2][n][o]);
            float r = g_r[((size_t)n * B + b) * O + o];
            float st = state[((size_t)b * N + n) * H + o];
            out[((size_t)b * N + n) * O + o] = r * st + (1.0f - r) * hc;
        }
    }
}

// ---------------- launch ----------------
extern "C" void kernel_launch(void* const* d_in, const int* in_sizes, int n_in,
                              void* d_out, int out_size) {
    const float* x     = (const float*)d_in[0];
    const float* state = (const float*)d_in[1];
    const float* ne    = (const float*)d_in[2];
    const float* te    = (const float*)d_in[3];
    const float* W_z   = (const float*)d_in[4];
    const float* b_z   = (const float*)d_in[5];
    const float* gam_z = (const float*)d_in[6];
    const float* bet_z = (const float*)d_in[7];
    const float* W_r   = (const float*)d_in[8];
    const float* b_r   = (const float*)d_in[9];
    const float* gam_r = (const float*)d_in[10];
    const float* bet_r = (const float*)d_in[11];
    const float* W_u   = (const float*)d_in[12];
    const float* b_u   = (const float*)d_in[13];
    const float* gam_u = (const float*)d_in[14];
    const float* bet_u = (const float*)d_in[15];
    float* out = (float*)d_out;

    cudaFuncSetAttribute(k_mmagemm, cudaFuncAttributeMaxDynamicSharedMemorySize, GEMM_SMEM);
    cudaFuncSetAttribute(k_gate_zr, cudaFuncAttributeMaxDynamicSharedMemorySize, GATE_SMEM);
    cudaFuncSetAttribute(k_final,   cudaFuncAttributeMaxDynamicSharedMemorySize, GATE_SMEM);

    k_flags<<<1, 32>>>(gam_z, bet_z, gam_r, bet_r, gam_u, bet_u);
    k_embed<<<N, 32>>>(ne, te, gam_z, bet_z, gam_r, bet_r, gam_u, bet_u);
    k_bias<<<(3 * N * O + 255) / 256, 256>>>(b_z, b_r, b_u);
    k_adj<<<dim3(N / 4, 3), 256>>>();
    k_buildXh<<<(N * BC + 255) / 256, 256>>>(x, state);
    k_wn<<<dim3(66, 32, 3), 256>>>(W_z, W_r, W_u);
    k_mmagemm<<<dim3(BC / 128, N / 128, 2), 256, GEMM_SMEM>>>(0, 0);   // Y_z (+Y_r if params differ)
    k_gate_zr<<<dim3(N, 2), 256, GATE_SMEM>>>(x, state);
    k_mmagemm<<<dim3(BC / 128, N / 128, 1), 256, GEMM_SMEM>>>(2, 1);   // Y_u = A_u @ Xc
    k_final<<<N, 256, GATE_SMEM>>>(state, out);
}

// round 8
// speedup vs baseline: 5.4563x; 1.2192x over previous
#include <cuda_runtime.h>
#include <cuda_fp16.h>
#include <cstdint>
#include <math.h>

// Problem constants
#define B   64
#define N   2048
#define D   16
#define H   64
#define DIN 2
#define C   66          // DIN + H
#define KI  132         // 2*C
#define KIP 144         // KI padded to multiple of 16
#define O   64
#define BC  (B*C)       // 4224

// ---------------- scratch (static __device__, no allocation) ----------------
__device__ int   g_same[2];                                   // [0]: r==z params, [1]: u==z params
__device__ float g_e[3][N][D];
__device__ float g_bias[3][N][O];
__device__ __align__(16) __half g_Af[3][(size_t)N * N];       // adjacency fp16 [m][k]
__device__ __align__(16) __half g_Xh[(size_t)N * BC];         // Xs fp16 [m][col]
__device__ __align__(16) __half g_Xch[(size_t)N * BC];        // Xc fp16 [m][col]
__device__ __align__(16) __half g_Yh[3][(size_t)N * BC];      // A @ X fp16
__device__ __align__(16) __half g_Wnh[3][(size_t)N * KI * O]; // per-node weights fp16
__device__ float g_r[(size_t)N * B * O];

__device__ __forceinline__ float sigmoidf_(float v) { return 1.0f / (1.0f + expf(-v)); }

__device__ __forceinline__ uint32_t smem_u32(const void* p) {
    uint32_t a;
    asm("{ .reg .u64 t; cvta.to.shared.u64 t, %1; cvt.u32.u64 %0, t; }" : "=r"(a) : "l"(p));
    return a;
}

#define LDM_X4(r, addr) \
    asm volatile("ldmatrix.sync.aligned.m8n8.x4.shared.b16 {%0,%1,%2,%3}, [%4];" \
        : "=r"((r)[0]), "=r"((r)[1]), "=r"((r)[2]), "=r"((r)[3]) : "r"(addr))
#define LDM_X4_T(r, addr) \
    asm volatile("ldmatrix.sync.aligned.m8n8.x4.trans.shared.b16 {%0,%1,%2,%3}, [%4];" \
        : "=r"((r)[0]), "=r"((r)[1]), "=r"((r)[2]), "=r"((r)[3]) : "r"(addr))

#define MMA_F16(d, a, b) \
    asm volatile("mma.sync.aligned.m16n8k16.row.col.f32.f16.f16.f32 " \
        "{%0,%1,%2,%3}, {%4,%5,%6,%7}, {%8,%9}, {%0,%1,%2,%3};" \
        : "+f"((d)[0]), "+f"((d)[1]), "+f"((d)[2]), "+f"((d)[3]) \
        : "r"((a)[0]), "r"((a)[1]), "r"((a)[2]), "r"((a)[3]), "r"((b)[0]), "r"((b)[1]))

#define CP_ASYNC16(smaddr, gptr) \
    asm volatile("cp.async.cg.shared.global [%0], [%1], 16;" :: "r"(smaddr), "l"(gptr) : "memory")
#define CP_COMMIT() asm volatile("cp.async.commit_group;" ::: "memory")
#define CP_WAIT1() asm volatile("cp.async.wait_group 1;" ::: "memory")
#define CP_WAIT0() asm volatile("cp.async.wait_group 0;" ::: "memory")

// ---------------- K0: runtime equality flags ----------------
__global__ void k_flags(const float* gz, const float* bz, const float* gr, const float* br,
                        const float* gu, const float* bu) {
    int t = threadIdx.x;
    bool okr = true, oku = true;
    if (t < D) {
        okr = (gr[t] == gz[t]) && (br[t] == bz[t]);
        oku = (gu[t] == gz[t]) && (bu[t] == bz[t]);
    }
    unsigned mr = __ballot_sync(0xffffffffu, okr);
    unsigned mu = __ballot_sync(0xffffffffu, oku);
    if (t == 0) { g_same[0] = (mr == 0xffffffffu); g_same[1] = (mu == 0xffffffffu); }
}

// ---------------- K1: layernorm embeddings ----------------
__global__ void k_embed(const float* __restrict__ ne, const float* __restrict__ te,
                        const float* __restrict__ gam_z, const float* __restrict__ bet_z,
                        const float* __restrict__ gam_r, const float* __restrict__ bet_r,
                        const float* __restrict__ gam_u, const float* __restrict__ bet_u) {
    int n = blockIdx.x;
    int t = threadIdx.x;
    float v = 0.f;
    if (t < D) v = ne[n * D + t] + te[t];
    float s = v;
    #pragma unroll
    for (int off = 16; off; off >>= 1) s += __shfl_xor_sync(0xffffffffu, s, off);
    float m = s * (1.0f / D);
    float d2 = (t < D) ? (v - m) * (v - m) : 0.f;
    #pragma unroll
    for (int off = 16; off; off >>= 1) d2 += __shfl_xor_sync(0xffffffffu, d2, off);
    float rs = rsqrtf(d2 * (1.0f / D) + 1e-12f);
    if (t < D) {
        float xn = (v - m) * rs;
        g_e[0][n][t] = xn * gam_z[t] + bet_z[t];
        g_e[1][n][t] = xn * gam_r[t] + bet_r[t];
        g_e[2][n][t] = xn * gam_u[t] + bet_u[t];
    }
}

// ---------------- K2: bias = e @ b_pool ----------------
__global__ void k_bias(const float* __restrict__ bz, const float* __restrict__ br,
                       const float* __restrict__ bu) {
    int idx = blockIdx.x * blockDim.x + threadIdx.x;
    if (idx >= 3 * N * O) return;
    int o = idx % O;
    int n = (idx / O) % N;
    int g = idx / (O * N);
    const float* bp = (g == 0) ? bz : (g == 1) ? br : bu;
    float acc = 0.f;
    #pragma unroll
    for (int d = 0; d < D; d++) acc += g_e[g][n][d] * bp[d * O + o];
    g_bias[g][n][o] = acc;
}

// ---------------- K3: adjacency softmax -> fp16 ----------------
__global__ void __launch_bounds__(256) k_adj() {
    int g = blockIdx.y;
    if (g > 0 && g_same[g - 1]) return;
    int n0 = blockIdx.x * 4;
    int t = threadIdx.x, lane = t & 31, w = t >> 5;
    __shared__ float er[4][16];
    __shared__ float redA[4][8];
    __shared__ float finM[4], finS[4];
    if (t < 64) er[t >> 4][t & 15] = g_e[g][n0 + (t >> 4)][t & 15];
    __syncthreads();

    float dots[4][8];
    float mx[4] = {-1e30f, -1e30f, -1e30f, -1e30f};
    #pragma unroll
    for (int i = 0; i < 8; i++) {
        int col = t + i * 256;
        const float4* em = (const float4*)&g_e[g][col][0];
        float4 e0 = em[0], e1 = em[1], e2 = em[2], e3 = em[3];
        float ec[16] = {e0.x, e0.y, e0.z, e0.w, e1.x, e1.y, e1.z, e1.w,
                        e2.x, e2.y, e2.z, e2.w, e3.x, e3.y, e3.z, e3.w};
        #pragma unroll
        for (int r = 0; r < 4; r++) {
            float d = 0.f;
            #pragma unroll
            for (int k = 0; k < 16; k++) d += er[r][k] * ec[k];
            dots[r][i] = d;
            mx[r] = fmaxf(mx[r], d);
        }
    }
    #pragma unroll
    for (int r = 0; r < 4; r++) {
        float m = mx[r];
        #pragma unroll
        for (int off = 16; off; off >>= 1) m = fmaxf(m, __shfl_xor_sync(0xffffffffu, m, off));
        if (lane == 0) redA[r][w] = m;
    }
    __syncthreads();
    if (t < 4) {
        float M = redA[t][0];
        #pragma unroll
        for (int j = 1; j < 8; j++) M = fmaxf(M, redA[t][j]);
        finM[t] = M;
    }
    __syncthreads();
    #pragma unroll
    for (int r = 0; r < 4; r++) {
        float M = finM[r];
        float s = 0.f;
        #pragma unroll
        for (int i = 0; i < 8; i++) { dots[r][i] = __expf(dots[r][i] - M); s += dots[r][i]; }
        #pragma unroll
        for (int off = 16; off; off >>= 1) s += __shfl_xor_sync(0xffffffffu, s, off);
        if (lane == 0) redA[r][w] = s;
    }
    __syncthreads();
    if (t < 4) {
        float S = 0.f;
        #pragma unroll
        for (int j = 0; j < 8; j++) S += redA[t][j];
        finS[t] = 1.0f / S;
    }
    __syncthreads();
    #pragma unroll
    for (int r = 0; r < 4; r++) {
        float inv = finS[r];
        __half* out = &g_Af[g][(size_t)(n0 + r) * N];
        #pragma unroll
        for (int i = 0; i < 8; i++) out[t + i * 256] = __float2half(dots[r][i] * inv);
    }
}

// ---------------- K4: build Xs fp16 [m][col] ----------------
__global__ void k_buildXh(const float* __restrict__ x, const float* __restrict__ state) {
    int idx = blockIdx.x * blockDim.x + threadIdx.x;
    if (idx >= N * BC) return;
    int m = idx / BC;
    int j = idx - m * BC;
    int b = j / C;
    int c = j - b * C;
    float v = (c < DIN) ? x[(b * N + m) * DIN + c] : state[(b * N + m) * H + (c - DIN)];
    g_Xh[idx] = __float2half(v);
}

// ---------------- K5: Wn = E @ W_pool via MMA (M=64 nodes, K=16, N=128 cols) ----------------
#define EPAD 24
#define WPADW 136
__global__ void __launch_bounds__(256) k_wn(const float* __restrict__ Wz, const float* __restrict__ Wr,
                                            const float* __restrict__ Wu) {
    int g = blockIdx.z;
    const float* W = (g == 0) ? Wz : (g == 1) ? Wr : Wu;
    int ioBase = blockIdx.x * 128;
    int nBase = blockIdx.y * 64;
    __shared__ __half Eh[64 * EPAD];
    __shared__ __half Wsh[16 * WPADW];
    int t = threadIdx.x, lane = t & 31, wid = t >> 5;

    for (int idx = t; idx < 64 * 16; idx += 256) {
        int r = idx >> 4, d = idx & 15;
        Eh[r * EPAD + d] = __float2half(g_e[g][nBase + r][d]);
    }
    for (int idx = t * 4; idx < 16 * 128; idx += 1024) {
        int d = idx >> 7, c = idx & 127;
        const float4 wv = *(const float4*)&W[(size_t)d * (KI * O) + ioBase + c];
        __half* dst = &Wsh[d * WPADW + c];
        dst[0] = __float2half(wv.x); dst[1] = __float2half(wv.y);
        dst[2] = __float2half(wv.z); dst[3] = __float2half(wv.w);
    }
    __syncthreads();

    int warp_m = wid & 1, warp_n = wid >> 1;   // 2 x 4
    uint32_t ue = smem_u32(Eh), uw = smem_u32(Wsh);
    uint32_t fa[2][4], fb[2][4];
    #pragma unroll
    for (int mt = 0; mt < 2; mt++) {
        uint32_t a = ue + (uint32_t)(((warp_m * 32 + mt * 16 + (lane & 15)) * EPAD + ((lane >> 4) << 3)) * 2);
        LDM_X4(fa[mt], a);
    }
    #pragma unroll
    for (int p = 0; p < 2; p++) {
        uint32_t bptr = uw + (uint32_t)(((lane & 15) * WPADW + warp_n * 32 + p * 16 + ((lane >> 4) << 3)) * 2);
        LDM_X4_T(fb[p], bptr);
    }
    float acc[2][4][4];
    #pragma unroll
    for (int i = 0; i < 2; i++)
        #pragma unroll
        for (int j = 0; j < 4; j++)
            #pragma unroll
            for (int q = 0; q < 4; q++) acc[i][j][q] = 0.f;
    #pragma unroll
    for (int mt = 0; mt < 2; mt++)
        #pragma unroll
        for (int p = 0; p < 2; p++) {
            MMA_F16(acc[mt][2 * p],     fa[mt], &fb[p][0]);
            MMA_F16(acc[mt][2 * p + 1], fa[mt], &fb[p][2]);
        }

    #pragma unroll
    for (int mt = 0; mt < 2; mt++) {
        int n = nBase + warp_m * 32 + mt * 16 + (lane >> 2);
        #pragma unroll
        for (int nt = 0; nt < 4; nt++) {
            int io = ioBase + warp_n * 32 + nt * 8 + (lane & 3) * 2;
            *(__half2*)&g_Wnh[g][(size_t)n * (KI * O) + io] = __floats2half2_rn(acc[mt][nt][0], acc[mt][nt][1]);
            *(__half2*)&g_Wnh[g][(size_t)(n + 8) * (KI * O) + io] = __floats2half2_rn(acc[mt][nt][2], acc[mt][nt][3]);
        }
    }
}

// ---------------- K6: mma.sync fp16 GEMM  Y = A @ X  (unchanged from R7) ----------------
#define APAD 40
#define BPAD 136
#define STG_A (128 * APAD)
#define STG_B (32 * BPAD)
#define STG   (STG_A + STG_B)
#define NCH   (N / 32)
#define GEMM_SMEM (3 * STG * 2)

__global__ void __launch_bounds__(256) k_mmagemm(int gate0, int useXc) {
    extern __shared__ __half gsm[];
    int t = threadIdx.x, lane = t & 31, wid = t >> 5;

    const __half* Aptr;
    __half* Yout;
    if (gate0 == 2) {
        Aptr = g_same[1] ? g_Af[0] : g_Af[2];
        Yout = g_Yh[2];
    } else {
        int gate = blockIdx.z;
        if (gate == 1 && g_same[0]) return;
        Aptr = g_Af[gate];
        Yout = g_Yh[gate];
    }
    const __half* Bptr = useXc ? g_Xch : g_Xh;

    int m0 = blockIdx.y * 128, c0 = blockIdx.x * 128;
    int warp_m = wid & 3, warp_n = wid >> 2;

    float acc[2][8][4];
    #pragma unroll
    for (int i = 0; i < 2; i++)
        #pragma unroll
        for (int j = 0; j < 8; j++)
            #pragma unroll
            for (int q = 0; q < 4; q++) acc[i][j][q] = 0.f;

    int arow = t >> 1, aseg = t & 1;
    const __half* gA = Aptr + (size_t)(m0 + arow) * N + aseg * 16;
    uint32_t sAoff = (uint32_t)(arow * APAD + aseg * 16) * 2;
    int brow = t >> 3, bseg = t & 7;
    const __half* gB = Bptr + c0 + bseg * 16;
    uint32_t sBoff = (uint32_t)(brow * BPAD + bseg * 16) * 2;

    uint32_t base = smem_u32(gsm);

    uint32_t aoff[2], boff[4];
    #pragma unroll
    for (int mt = 0; mt < 2; mt++)
        aoff[mt] = (uint32_t)(((warp_m * 32 + mt * 16 + (lane & 15)) * APAD + ((lane >> 4) << 3)) * 2);
    #pragma unroll
    for (int p = 0; p < 4; p++)
        boff[p] = (uint32_t)(((lane & 15) * BPAD + warp_n * 64 + p * 16 + ((lane >> 4) << 3)) * 2);

    #define ISSUE(kc, s) do { \
        const __half* pa = gA + (size_t)(kc) * 32; \
        const __half* pb = gB + (size_t)((kc) * 32 + brow) * BC; \
        uint32_t da = base + (s) * (STG * 2) + sAoff; \
        uint32_t db = base + (s) * (STG * 2) + STG_A * 2 + sBoff; \
        CP_ASYNC16(da, pa); CP_ASYNC16(da + 16, pa + 8); \
        CP_ASYNC16(db, pb); CP_ASYNC16(db + 16, pb + 8); \
        CP_COMMIT(); \
    } while (0)

    ISSUE(0, 0);
    ISSUE(1, 1);

    for (int kc = 0; kc < NCH; kc++) {
        int st = kc % 3;
        if (kc == NCH - 1) { CP_WAIT0(); } else { CP_WAIT1(); }
        __syncthreads();
        if (kc + 2 < NCH) ISSUE(kc + 2, (kc + 2) % 3);

        uint32_t ua = base + st * (STG * 2);
        uint32_t ub = ua + STG_A * 2;
        #pragma unroll
        for (int ks = 0; ks < 2; ks++) {
            uint32_t fa[2][4], fb[4][4];
            #pragma unroll
            for (int mt = 0; mt < 2; mt++) LDM_X4(fa[mt], ua + aoff[mt] + ks * 32);
            #pragma unroll
            for (int p = 0; p < 4; p++) LDM_X4_T(fb[p], ub + boff[p] + ks * 16 * BPAD * 2);
            #pragma unroll
            for (int mt = 0; mt < 2; mt++) {
                #pragma unroll
                for (int p = 0; p < 4; p++) {
                    MMA_F16(acc[mt][2 * p],     fa[mt], &fb[p][0]);
                    MMA_F16(acc[mt][2 * p + 1], fa[mt], &fb[p][2]);
                }
            }
        }
    }
    #undef ISSUE

    #pragma unroll
    for (int mt = 0; mt < 2; mt++) {
        int r = m0 + warp_m * 32 + mt * 16 + (lane >> 2);
        #pragma unroll
        for (int nt = 0; nt < 8; nt++) {
            int cc = c0 + warp_n * 64 + nt * 8 + (lane & 3) * 2;
            *(__half2*)&Yout[(size_t)r * BC + cc] = __floats2half2_rn(acc[mt][nt][0], acc[mt][nt][1]);
            *(__half2*)&Yout[(size_t)(r + 8) * BC + cc] = __floats2half2_rn(acc[mt][nt][2], acc[mt][nt][3]);
        }
    }
}

// ---------------- shared helper: per-node gate mini-GEMM via MMA ----------------
// Xall [64 b][KIP] fp16, Wh [KIP][O] fp16 (trans-read). acc[mt][nt][4], warp 32x16.
#define XPAD 152
#define WPAD 72

// loads + mma for one (node, gate); returns acc in-place
__device__ __forceinline__ void gate_mma(__half* Xall, __half* Wh,
                                         const __half* __restrict__ xsrc,
                                         const __half* __restrict__ ysrc,
                                         const __half* __restrict__ wsrc,
                                         int t, int lane, int wid,
                                         float acc[2][2][4]) {
    // load Wn rows 0..131, zero 132..143
    for (int cid = t; cid < (KI * O) / 8; cid += 256) {
        int r = cid >> 3, c8 = (cid & 7) * 8;
        *(uint4*)&Wh[r * WPAD + c8] = *(const uint4*)&wsrc[r * O + c8];
    }
    for (int cid = t; cid < 12 * 8; cid += 256) {
        int r = KI + (cid >> 3), c8 = (cid & 7) * 8;
        *(uint4*)&Wh[r * WPAD + c8] = make_uint4(0, 0, 0, 0);
    }
    // build Xall
    for (int idx = t; idx < BC; idx += 256) {
        int b = idx / C, c = idx - b * C;
        Xall[b * XPAD + c] = xsrc[idx];
        Xall[b * XPAD + C + c] = ysrc[idx];
    }
    for (int idx = t; idx < 64 * 12; idx += 256) {
        int b = idx / 12, c = KI + idx % 12;
        Xall[b * XPAD + c] = __ushort_as_half((unsigned short)0);
    }
    __syncthreads();

    int warp_m = wid & 1, warp_n = wid >> 1;  // 2 x 4
    uint32_t ax = smem_u32(Xall), wx = smem_u32(Wh);
    uint32_t aoff[2];
    #pragma unroll
    for (int mt = 0; mt < 2; mt++)
        aoff[mt] = (uint32_t)(((warp_m * 32 + mt * 16 + (lane & 15)) * XPAD + ((lane >> 4) << 3)) * 2);
    uint32_t boff = (uint32_t)(((lane & 15) * WPAD + warp_n * 16 + ((lane >> 4) << 3)) * 2);

    #pragma unroll
    for (int ks = 0; ks < KIP / 16; ks++) {
        uint32_t fa[2][4], fb[4];
        LDM_X4(fa[0], ax + aoff[0] + ks * 32);
        LDM_X4(fa[1], ax + aoff[1] + ks * 32);
        LDM_X4_T(fb, wx + boff + (uint32_t)(ks * 16 * WPAD * 2));
        #pragma unroll
        for (int mt = 0; mt < 2; mt++) {
            MMA_F16(acc[mt][0], fa[mt], &fb[0]);
            MMA_F16(acc[mt][1], fa[mt], &fb[2]);
        }
    }
}

// ---------------- K7: z/r gate apply (MMA) ----------------
__global__ void __launch_bounds__(256) k_gate_zr(const float* __restrict__ state) {
    __shared__ __half Xall[64 * XPAD];
    __shared__ __half Wh[KIP * WPAD];
    int n = blockIdx.x;
    int g = blockIdx.y;  // 0 = z, 1 = r
    int t = threadIdx.x, lane = t & 31, wid = t >> 5;

    const __half* xsrc = g_Xh + (size_t)n * BC;
    const __half* ysrc = ((g == 1) && g_same[0]) ? (g_Yh[0] + (size_t)n * BC)
                                                 : (g_Yh[g] + (size_t)n * BC);
    const __half* wsrc = g_Wnh[g] + (size_t)n * (KI * O);

    float acc[2][2][4];
    #pragma unroll
    for (int i = 0; i < 2; i++)
        #pragma unroll
        for (int j = 0; j < 2; j++)
            #pragma unroll
            for (int q = 0; q < 4; q++) acc[i][j][q] = 0.f;

    gate_mma(Xall, Wh, xsrc, ysrc, wsrc, t, lane, wid, acc);

    int warp_m = wid & 1, warp_n = wid >> 1;
    #pragma unroll
    for (int mt = 0; mt < 2; mt++) {
        int b = warp_m * 32 + mt * 16 + (lane >> 2);
        #pragma unroll
        for (int nt = 0; nt < 2; nt++) {
            int o = warp_n * 16 + nt * 8 + (lane & 3) * 2;
            #pragma unroll
            for (int half_ = 0; half_ < 2; half_++) {
                int bb = b + half_ * 8;
                float2 bi = *(const float2*)&g_bias[g][n][o];
                float v0 = acc[mt][nt][2 * half_ + 0] + bi.x;
                float v1 = acc[mt][nt][2 * half_ + 1] + bi.y;
                float s0 = sigmoidf_(v0), s1 = sigmoidf_(v1);
                if (g == 0) {
                    float st0 = state[((size_t)bb * N + n) * H + o];
                    float st1 = state[((size_t)bb * N + n) * H + o + 1];
                    *(__half2*)&g_Xch[(size_t)n * BC + bb * C + DIN + o] =
                        __floats2half2_rn(s0 * st0, s1 * st1);
                } else {
                    *(float2*)&g_r[((size_t)n * B + bb) * O + o] = make_float2(s0, s1);
                }
            }
        }
    }
    // x columns of Xc
    if (g == 0 && t < B * DIN) {
        int b = t >> 1, c = t & 1;
        g_Xch[(size_t)n * BC + b * C + c] = xsrc[b * C + c];
    }
}

// ---------------- K8: final u gate + GRU combine (MMA) ----------------
__global__ void __launch_bounds__(256) k_final(const float* __restrict__ state, float* __restrict__ out) {
    __shared__ __half Xall[64 * XPAD];
    __shared__ __half Wh[KIP * WPAD];
    int n = blockIdx.x;
    int t = threadIdx.x, lane = t & 31, wid = t >> 5;

    const __half* xsrc = g_Xch + (size_t)n * BC;
    const __half* ysrc = g_Yh[2] + (size_t)n * BC;
    const __half* wsrc = g_Wnh[2] + (size_t)n * (KI * O);

    float acc[2][2][4];
    #pragma unroll
    for (int i = 0; i < 2; i++)
        #pragma unroll
        for (int j = 0; j < 2; j++)
            #pragma unroll
            for (int q = 0; q < 4; q++) acc[i][j][q] = 0.f;

    gate_mma(Xall, Wh, xsrc, ysrc, wsrc, t, lane, wid, acc);

    int warp_m = wid & 1, warp_n = wid >> 1;
    #pragma unroll
    for (int mt = 0; mt < 2; mt++) {
        int b = warp_m * 32 + mt * 16 + (lane >> 2);
        #pragma unroll
        for (int nt = 0; nt < 2; nt++) {
            int o = warp_n * 16 + nt * 8 + (lane & 3) * 2;
            #pragma unroll
            for (int half_ = 0; half_ < 2; half_++) {
                int bb = b + half_ * 8;
                float2 bi = *(const float2*)&g_bias[2][n][o];
                float hc0 = tanhf(acc[mt][nt][2 * half_ + 0] + bi.x);
                float hc1 = tanhf(acc[mt][nt][2 * half_ + 1] + bi.y);
                float2 rr = *(const float2*)&g_r[((size_t)n * B + bb) * O + o];
                float st0 = state[((size_t)bb * N + n) * H + o];
                float st1 = state[((size_t)bb * N + n) * H + o + 1];
                *(float2*)&out[((size_t)bb * N + n) * O + o] =
                    make_float2(rr.x * st0 + (1.0f - rr.x) * hc0,
                                rr.y * st1 + (1.0f - rr.y) * hc1);
            }
        }
    }
}

// ---------------- launch ----------------
extern "C" void kernel_launch(void* const* d_in, const int* in_sizes, int n_in,
                              void* d_out, int out_size) {
    const float* x     = (const float*)d_in[0];
    const float* state = (const float*)d_in[1];
    const float* ne    = (const float*)d_in[2];
    const float* te    = (const float*)d_in[3];
    const float* W_z   = (const float*)d_in[4];
    const float* b_z   = (const float*)d_in[5];
    const float* gam_z = (const float*)d_in[6];
    const float* bet_z = (const float*)d_in[7];
    const float* W_r   = (const float*)d_in[8];
    const float* b_r   = (const float*)d_in[9];
    const float* gam_r = (const float*)d_in[10];
    const float* bet_r = (const float*)d_in[11];
    const float* W_u   = (const float*)d_in[12];
    const float* b_u   = (const float*)d_in[13];
    const float* gam_u = (const float*)d_in[14];
    const float* bet_u = (const float*)d_in[15];
    float* out = (float*)d_out;

    cudaFuncSetAttribute(k_mmagemm, cudaFuncAttributeMaxDynamicSharedMemorySize, GEMM_SMEM);

    k_flags<<<1, 32>>>(gam_z, bet_z, gam_r, bet_r, gam_u, bet_u);
    k_embed<<<N, 32>>>(ne, te, gam_z, bet_z, gam_r, bet_r, gam_u, bet_u);
    k_bias<<<(3 * N * O + 255) / 256, 256>>>(b_z, b_r, b_u);
    k_adj<<<dim3(N / 4, 3), 256>>>();
    k_buildXh<<<(N * BC + 255) / 256, 256>>>(x, state);
    k_wn<<<dim3(66, 32, 3), 256>>>(W_z, W_r, W_u);
    k_mmagemm<<<dim3(BC / 128, N / 128, 2), 256, GEMM_SMEM>>>(0, 0);   // Y_z (+Y_r if needed)
    k_gate_zr<<<dim3(N, 2), 256>>>(state);
    k_mmagemm<<<dim3(BC / 128, N / 128, 1), 256, GEMM_SMEM>>>(2, 1);   // Y_u = A_u @ Xc
    k_final<<<N, 256>>>(state, out);
}